// round 12
// baseline (speedup 1.0000x reference)
#include <cuda_runtime.h>
#include <cuda_fp16.h>
#include <math.h>
#include <stdint.h>

#if defined(__CUDA_ARCH_FEAT_SM103_ALL) || defined(__CUDA_ARCH_FEAT_SM100_ALL)
#define HAS_TCGEN05 1
#else
#define HAS_TCGEN05 0
#endif

#define S_LEN 8192
#define D_DIM 256
#define BM 128
#define BN 64
#define NSPLIT 2
#define KV_PER (S_LEN / NSPLIT)
#define NIT (KV_PER / BN)
#define THREADS 384
#define HTHREADS 256

// ---------------- device scratch (allocation-free) ----------------
__device__ __half g_Qh[S_LEN * D_DIM];
__device__ __half g_Kh[S_LEN * D_DIM];
__device__ __half g_Vh[S_LEN * D_DIM];          // row-major V (HMMA fallback only)
__device__ __half g_Vt[D_DIM * S_LEN];          // transposed V (tcgen05 path)
__device__ float  g_Op[NSPLIT][S_LEN * D_DIM];  // unnormalized O per split
__device__ float  g_lsum[NSPLIT][2][S_LEN];     // partial exp-sums (per split, per col-half)

__global__ void convert_kernel(const float* __restrict__ Q,
                               const float* __restrict__ K,
                               const float* __restrict__ V) {
    int i = blockIdx.x * blockDim.x + threadIdx.x;   // over n/4
    if (i < S_LEN * D_DIM / 4) {
        const float4 q = reinterpret_cast<const float4*>(Q)[i];
        const float4 k = reinterpret_cast<const float4*>(K)[i];
#if HAS_TCGEN05
        const float scale = rsqrtf((float)S_LEN) * 1.4426950408889634f;  // fold log2(e)
        __half2* qh = reinterpret_cast<__half2*>(g_Qh) + 2 * i;
        __half2* kh = reinterpret_cast<__half2*>(g_Kh) + 2 * i;
        qh[0] = __floats2half2_rn(q.x * scale, q.y * scale);
        qh[1] = __floats2half2_rn(q.z * scale, q.w * scale);
        kh[0] = __floats2half2_rn(k.x, k.y);
        kh[1] = __floats2half2_rn(k.z, k.w);
#else
        const float scale = rsqrtf((float)S_LEN);
        const float4 v = reinterpret_cast<const float4*>(V)[i];
        __half2* qh = reinterpret_cast<__half2*>(g_Qh) + 2 * i;
        __half2* kh = reinterpret_cast<__half2*>(g_Kh) + 2 * i;
        __half2* vh = reinterpret_cast<__half2*>(g_Vh) + 2 * i;
        qh[0] = __floats2half2_rn(q.x * scale, q.y * scale);
        qh[1] = __floats2half2_rn(q.z * scale, q.w * scale);
        kh[0] = __floats2half2_rn(k.x, k.y);
        kh[1] = __floats2half2_rn(k.z, k.w);
        vh[0] = __floats2half2_rn(v.x, v.y);
        vh[1] = __floats2half2_rn(v.z, v.w);
#endif
    }
}

// V [S, D] f32 -> g_Vt [D, S] f16 (tiled transpose)
__global__ void transposeV_kernel(const float* __restrict__ V) {
    __shared__ float tile[32][33];
    const int bx = blockIdx.x * 32;   // d base
    const int by = blockIdx.y * 32;   // s base
    const int tx = threadIdx.x, ty = threadIdx.y;   // 32 x 8
    #pragma unroll
    for (int j = 0; j < 32; j += 8)
        tile[ty + j][tx] = V[(size_t)(by + ty + j) * D_DIM + bx + tx];
    __syncthreads();
    #pragma unroll
    for (int j = 0; j < 32; j += 8)
        g_Vt[(size_t)(bx + ty + j) * S_LEN + by + tx] = __float2half(tile[tx][ty + j]);
}

__global__ void combine_kernel(float* __restrict__ out) {
    int i = blockIdx.x * blockDim.x + threadIdx.x;   // over n/4
    if (i < S_LEN * D_DIM / 4) {
        int row = i >> 6;   // (4*i)>>8
        float4 a = reinterpret_cast<const float4*>(g_Op[0])[i];
        float4 b = reinterpret_cast<const float4*>(g_Op[1])[i];
        float inv = 1.f / (g_lsum[0][0][row] + g_lsum[0][1][row] +
                           g_lsum[1][0][row] + g_lsum[1][1][row]);
        float4 o;
        o.x = (a.x + b.x) * inv; o.y = (a.y + b.y) * inv;
        o.z = (a.z + b.z) * inv; o.w = (a.w + b.w) * inv;
        reinterpret_cast<float4*>(out)[i] = o;
    }
}

// ---------------- common PTX helpers ----------------
__device__ __forceinline__ uint32_t sptr(const void* p) {
    return (uint32_t)__cvta_generic_to_shared(p);
}
__device__ __forceinline__ void cp16(uint32_t s, const void* g) {
    asm volatile("cp.async.cg.shared.global [%0], [%1], 16;\n" :: "r"(s), "l"(g));
}
__device__ __forceinline__ void cp_commit() { asm volatile("cp.async.commit_group;\n"); }

#if HAS_TCGEN05
__device__ __forceinline__ void cp_wait1()  { asm volatile("cp.async.wait_group 1;\n" ::: "memory"); }
#endif
__device__ __forceinline__ void cp_wait0()  { asm volatile("cp.async.wait_group 0;\n" ::: "memory"); }

// fast exp2 via MUFU.EX2 (flag-independent)
__device__ __forceinline__ float ex2(float x) {
    float r;
    asm("ex2.approx.ftz.f32 %0, %1;" : "=f"(r) : "f"(x));
    return r;
}

#if HAS_TCGEN05
__device__ __forceinline__ void fence_proxy() {
    asm volatile("fence.proxy.async.shared::cta;" ::: "memory");
}
__device__ __forceinline__ bool elect1() {
    uint32_t p;
    asm volatile("{\n\t.reg .pred p;\n\telect.sync _|p, 0xFFFFFFFF;\n\tselp.b32 %0, 1, 0, p;\n\t}"
                 : "=r"(p));
    return p != 0;
}
__device__ __forceinline__ void mb_init(uint32_t a, uint32_t c) {
    asm volatile("mbarrier.init.shared.b64 [%0], %1;" :: "r"(a), "r"(c) : "memory");
}
__device__ __forceinline__ void mb_arrive(uint32_t a) {
    asm volatile("mbarrier.arrive.shared.b64 _, [%0];" :: "r"(a) : "memory");
}
__device__ __forceinline__ void mb_wait(uint32_t a, uint32_t ph) {
    asm volatile(
        "{\n\t.reg .pred P;\n\t"
        "WL%=:\n\t"
        "mbarrier.try_wait.parity.acquire.cta.shared::cta.b64 P, [%0], %1, 0x989680;\n\t"
        "@P bra WD%=;\n\t"
        "bra WL%=;\n\t"
        "WD%=:\n\t}"
        :: "r"(a), "r"(ph) : "memory");
}
__device__ __forceinline__ void tc_alloc(uint32_t dst, uint32_t n) {
    asm volatile("tcgen05.alloc.cta_group::1.sync.aligned.shared::cta.b32 [%0], %1;"
                 :: "r"(dst), "r"(n) : "memory");
}
__device__ __forceinline__ void tc_relinq() {
    asm volatile("tcgen05.relinquish_alloc_permit.cta_group::1.sync.aligned;");
}
__device__ __forceinline__ void tc_dealloc(uint32_t t, uint32_t n) {
    asm volatile("tcgen05.dealloc.cta_group::1.sync.aligned.b32 %0, %1;" :: "r"(t), "r"(n));
}
__device__ __forceinline__ void tc_fence_before() {
    asm volatile("tcgen05.fence::before_thread_sync;" ::: "memory");
}
__device__ __forceinline__ void tc_fence_after() {
    asm volatile("tcgen05.fence::after_thread_sync;" ::: "memory");
}
__device__ __forceinline__ void tc_wait_ld() {
    asm volatile("tcgen05.wait::ld.sync.aligned;" ::: "memory");
}
__device__ __forceinline__ void tc_wait_st() {
    asm volatile("tcgen05.wait::st.sync.aligned;" ::: "memory");
}
__device__ __forceinline__ void tc_commit(uint32_t mbar) {
    asm volatile("tcgen05.commit.cta_group::1.mbarrier::arrive::one.shared::cluster.b64 [%0];"
                 :: "r"(mbar) : "memory");
}
__device__ __forceinline__ void mma_f16_ss(uint32_t d, uint64_t a, uint64_t b,
                                           uint32_t idesc, uint32_t en) {
    asm volatile(
        "{\n\t.reg .pred p;\n\tsetp.ne.u32 p, %4, 0;\n\t"
        "tcgen05.mma.cta_group::1.kind::f16 [%0], %1, %2, %3, {%5,%5,%5,%5}, p;\n\t}"
        :: "r"(d), "l"(a), "l"(b), "r"(idesc), "r"(en), "r"(0u) : "memory");
}
__device__ __forceinline__ void mma_f16_ts(uint32_t d, uint32_t a, uint64_t b,
                                           uint32_t idesc, uint32_t en) {
    asm volatile(
        "{\n\t.reg .pred p;\n\tsetp.ne.u32 p, %4, 0;\n\t"
        "tcgen05.mma.cta_group::1.kind::f16 [%0], [%1], %2, %3, {%5,%5,%5,%5}, p;\n\t}"
        :: "r"(d), "r"(a), "l"(b), "r"(idesc), "r"(en), "r"(0u) : "memory");
}

#define LDTM_LIST "{%0,%1,%2,%3,%4,%5,%6,%7,%8,%9,%10,%11,%12,%13,%14,%15,%16,%17,%18,%19,%20,%21,%22,%23,%24,%25,%26,%27,%28,%29,%30,%31}"
__device__ __forceinline__ void ldtm32(uint32_t* r, uint32_t a) {
    asm volatile("tcgen05.ld.sync.aligned.32x32b.x32.b32 " LDTM_LIST ", [%32];"
        : "=r"(r[0]), "=r"(r[1]), "=r"(r[2]), "=r"(r[3]), "=r"(r[4]), "=r"(r[5]), "=r"(r[6]), "=r"(r[7]),
          "=r"(r[8]), "=r"(r[9]), "=r"(r[10]), "=r"(r[11]), "=r"(r[12]), "=r"(r[13]), "=r"(r[14]), "=r"(r[15]),
          "=r"(r[16]), "=r"(r[17]), "=r"(r[18]), "=r"(r[19]), "=r"(r[20]), "=r"(r[21]), "=r"(r[22]), "=r"(r[23]),
          "=r"(r[24]), "=r"(r[25]), "=r"(r[26]), "=r"(r[27]), "=r"(r[28]), "=r"(r[29]), "=r"(r[30]), "=r"(r[31])
        : "r"(a));
}
__device__ __forceinline__ void sttm16(uint32_t a, const uint32_t* r) {
    asm volatile("tcgen05.st.sync.aligned.32x32b.x16.b32 [%0], "
        "{%1,%2,%3,%4,%5,%6,%7,%8,%9,%10,%11,%12,%13,%14,%15,%16};"
        :: "r"(a),
           "r"(r[0]), "r"(r[1]), "r"(r[2]), "r"(r[3]), "r"(r[4]), "r"(r[5]), "r"(r[6]), "r"(r[7]),
           "r"(r[8]), "r"(r[9]), "r"(r[10]), "r"(r[11]), "r"(r[12]), "r"(r[13]), "r"(r[14]), "r"(r[15])
        : "memory");
}
#endif  // HAS_TCGEN05

// ---------------- tcgen05 SMEM layout (relative to 1024-aligned base) ----------------
#define SM_Q    1024
#define SM_K(s) (SM_Q + BM * D_DIM * 2 + (s) * (BN * D_DIM * 2))
#define SM_V(s) (SM_Q + BM * D_DIM * 2 + 3 * (BN * D_DIM * 2) + (s) * (BN * D_DIM * 2))
#define SMEM_TOTAL (SM_V(2) + 1024)

// mbarrier offsets (within 1KB header)
#define MB_KRDY(s)  (16 + 8 * (s))    // K stage loaded       (count 64)
#define MB_VRDY(s)  (48 + 8 * (s))    // V stage loaded       (count 64)
#define MB_SQK(s)   (80 + 8 * (s))    // QK commit (S ready / K free)  (count 1)
#define MB_PVC(b)   (112 + 8 * (b))   // PV commit (V free / P free)   (count 1)
#define MB_SFREE(s) (144 + 8 * (s))   // S read by softmax    (count 256)
#define MB_PRDY(b)  (176 + 8 * (b))   // P written            (count 256)

// TMEM columns: S 3x64 @0, P 2x32 @192, O 256 @256
#define TM_S(s)  (64u * (s))
#define TM_P(b)  (192u + 32u * (b))
#define TM_O     256u

// K-major blocked-atom swizzled offset. r: row, c8: 16B chunk, natr: rows/8
__device__ __forceinline__ uint32_t kmaj_off(int r, int c8, int natr) {
    uint32_t b = (uint32_t)((c8 >> 3) * natr + (r >> 3)) * 1024u
               + (uint32_t)(r & 7) * 128u + (uint32_t)(c8 & 7) * 16u;
    return b ^ ((b >> 3) & 0x70u);
}

#define DESC_KMAJ ((2ull << 61) | (1ull << 46) | (64ull << 32) | (1ull << 16))
#define IDESC_F16 ((1u << 4) | (8u << 17) | (8u << 24))   // f32 accum, f16 in, N=64, M=128

__global__ __launch_bounds__(THREADS, 1)
void fa_tc_kernel() {
#if HAS_TCGEN05
    extern __shared__ char smraw[];
    const uint32_t smb = (sptr(smraw) + 1023u) & ~1023u;
    const int tid = threadIdx.x;
    const int warp = tid >> 5, lane = tid & 31;
    const int qblk = blockIdx.x >> 1;
    const int split = blockIdx.x & 1;
    const int m0 = qblk * BM;
    const size_t kv0 = (size_t)split * KV_PER;

    if (warp == 8) { tc_alloc(smb, 512); tc_relinq(); }
    if (tid == 0) {
        #pragma unroll
        for (int s = 0; s < 3; s++) {
            mb_init(smb + MB_KRDY(s), 64);
            mb_init(smb + MB_SQK(s), 1);
            mb_init(smb + MB_SFREE(s), 256);
        }
        #pragma unroll
        for (int b = 0; b < 2; b++) {
            mb_init(smb + MB_VRDY(b), 64);
            mb_init(smb + MB_PVC(b), 1);
            mb_init(smb + MB_PRDY(b), 256);
        }
    }
    // Q tile -> SMEM (all threads)
    {
        const __half* gq = g_Qh + (size_t)m0 * D_DIM;
        for (int i = tid; i < BM * (D_DIM / 8); i += THREADS) {
            int r = i >> 5, c8 = i & 31;
            cp16(smb + SM_Q + kmaj_off(r, c8, 16), gq + r * D_DIM + c8 * 8);
        }
        cp_commit(); cp_wait0();
    }
    fence_proxy();
    __syncthreads();
    uint32_t tmem;
    asm volatile("ld.shared.b32 %0, [%1];" : "=r"(tmem) : "r"(smb));

    if (warp >= 10) {
        // ================= loader warps (10,11) =================
        const int ltid = tid - 320;
        int phKf[3] = {0, 0, 0};   // K stage free (SQK flips)
        int phVf[2] = {0, 0};      // V stage free (PVC flips)
        for (int it = 0; it < NIT; ++it) {
            const int s3 = it % 3, s2 = it & 1;
            if (it >= 3) { mb_wait(smb + MB_SQK(s3), phKf[s3]); phKf[s3] ^= 1; }
            const __half* gk = g_Kh + (kv0 + (size_t)it * BN) * D_DIM;
            const uint32_t sk = smb + SM_K(s3);
            for (int i = ltid; i < BN * (D_DIM / 8); i += 64) {
                int r = i >> 5, c8 = i & 31;
                cp16(sk + kmaj_off(r, c8, 8), gk + r * D_DIM + c8 * 8);
            }
            cp_commit();                       // group: K
            if (it >= 2) { mb_wait(smb + MB_PVC(s2), phVf[s2]); phVf[s2] ^= 1; }
            const __half* gvt = g_Vt + kv0 + (size_t)it * BN;
            const uint32_t sv = smb + SM_V(s2);
            for (int i = ltid; i < D_DIM * (BN / 8); i += 64) {
                int r = i >> 3, c8 = i & 7;
                cp16(sv + kmaj_off(r, c8, 32), gvt + (size_t)r * S_LEN + c8 * 8);
            }
            cp_commit();                       // group: V
            cp_wait1();                        // K group done
            fence_proxy();
            mb_arrive(smb + MB_KRDY(s3));
            cp_wait0();                        // V group done
            fence_proxy();
            mb_arrive(smb + MB_VRDY(s2));
        }
    } else if (warp == 8) {
        // ================= QK issuer warp =================
        const uint64_t qd = DESC_KMAJ | (((uint64_t)(smb + SM_Q) >> 4) & 0x3FFFull);
        const uint64_t kd[3] = {
            DESC_KMAJ | (((uint64_t)(smb + SM_K(0)) >> 4) & 0x3FFFull),
            DESC_KMAJ | (((uint64_t)(smb + SM_K(1)) >> 4) & 0x3FFFull),
            DESC_KMAJ | (((uint64_t)(smb + SM_K(2)) >> 4) & 0x3FFFull) };
        int phKr[3] = {0, 0, 0};   // KRDY
        int phSf[3] = {0, 0, 0};   // SFREE
        for (int it = 0; it < NIT; ++it) {
            const int s = it % 3;
            mb_wait(smb + MB_KRDY(s), phKr[s]); phKr[s] ^= 1;
            if (it >= 3) { mb_wait(smb + MB_SFREE(s), phSf[s]); phSf[s] ^= 1; }
            tc_fence_after();
            if (elect1()) {
                for (int k = 0; k < 16; k++)
                    mma_f16_ss(tmem + TM_S(s), qd + ((k >> 2) * 1024 + (k & 3) * 2),
                               kd[s] + ((k >> 2) * 512 + (k & 3) * 2), IDESC_F16, k > 0);
                tc_commit(smb + MB_SQK(s));
            }
        }
    } else if (warp == 9) {
        // ================= PV issuer warp =================
        const uint64_t vd[2] = {
            DESC_KMAJ | (((uint64_t)(smb + SM_V(0)) >> 4) & 0x3FFFull),
            DESC_KMAJ | (((uint64_t)(smb + SM_V(1)) >> 4) & 0x3FFFull) };
        int phVr[2] = {0, 0};      // VRDY
        int phPr[2] = {0, 0};      // PRDY
        for (int it = 0; it < NIT; ++it) {
            const int b = it & 1;
            mb_wait(smb + MB_VRDY(b), phVr[b]); phVr[b] ^= 1;
            mb_wait(smb + MB_PRDY(b), phPr[b]); phPr[b] ^= 1;
            tc_fence_after();
            if (elect1()) {
                for (int c = 0; c < 4; c++)
                    for (int k = 0; k < 4; k++)
                        mma_f16_ts(tmem + TM_O + 64 * c, tmem + TM_P(b) + 8 * k,
                                   vd[b] + 512 * c + 2 * k, IDESC_F16, (it > 0) || (k > 0));
                tc_commit(smb + MB_PVC(b));
            }
        }
    } else {
        // ===== softmax warps (0-7): subpartition warp%4, column-half warp/4 =====
        // Prefetch-at-END pipeline (PRDY arrives before SQK(it+1) wait).
        const int sub = warp & 3;
        const int half = warp >> 2;
        const uint32_t woff = (uint32_t)sub << 21;
        const uint32_t scol = (uint32_t)half * 32;   // S col offset (fp32 cols)
        const uint32_t pcol = (uint32_t)half * 16;   // P col offset (b32 = 2 f16)
        int phS[3] = {0, 0, 0};    // SQK (S ready)
        int phPv[2] = {0, 0};      // PVC (P free)
        float lacc = 0.f;
        uint32_t rA[32], rB[32];

        auto sm_step = [&](int it, uint32_t* rc, uint32_t* rn) {
            const int b = it & 1;
            tc_wait_ld();                        // rc (tile it) in registers
            mb_arrive(smb + MB_SFREE(it % 3));   // S stage reusable by QK(it+3)
            uint32_t pk[16];
            #pragma unroll
            for (int j = 0; j < 16; j++) {
                float e0 = ex2(__uint_as_float(rc[2 * j]));
                float e1 = ex2(__uint_as_float(rc[2 * j + 1]));
                lacc += e0 + e1;
                __half2 h = __floats2half2_rn(e0, e1);
                pk[j] = *reinterpret_cast<uint32_t*>(&h);
            }
            if (it >= 2) { mb_wait(smb + MB_PVC(b), phPv[b]); phPv[b] ^= 1; }
            tc_fence_after();
            sttm16(tmem + TM_P(b) + woff + pcol, pk);
            tc_wait_st();
            tc_fence_before();
            mb_arrive(smb + MB_PRDY(b));
            // prefetch S(it+1) AFTER PRDY: off PV's critical path
            if (it + 1 < NIT) {
                const int sn = (it + 1) % 3;
                mb_wait(smb + MB_SQK(sn), phS[sn]); phS[sn] ^= 1;
                tc_fence_after();
                ldtm32(rn, tmem + TM_S(sn) + woff + scol);
            }
        };

        // prologue: load S(0)
        mb_wait(smb + MB_SQK(0), phS[0]); phS[0] ^= 1;
        tc_fence_after();
        ldtm32(rA, tmem + TM_S(0) + woff + scol);
        for (int it = 0; it < NIT; it += 2) {    // NIT even
            sm_step(it, rA, rB);
            sm_step(it + 1, rB, rA);
        }
        // epilogue: wait last PV, read O (each warp: 128 cols of its 32 rows)
        {
            const int lb = (NIT - 1) & 1;
            mb_wait(smb + MB_PVC(lb), phPv[lb]);
            tc_fence_after();
            const int row = m0 + (sub << 5) + lane;
            g_lsum[split][half][row] = lacc;
            float* op = g_Op[split] + (size_t)row * D_DIM + half * 128;
            for (int c = 0; c < 4; c++) {
                uint32_t r0[32];
                ldtm32(r0, tmem + TM_O + half * 128 + c * 32 + woff);
                tc_wait_ld();
                float4* dst = reinterpret_cast<float4*>(op + 32 * c);
                #pragma unroll
                for (int j = 0; j < 8; j++)
                    dst[j] = make_float4(__uint_as_float(r0[4 * j]), __uint_as_float(r0[4 * j + 1]),
                                         __uint_as_float(r0[4 * j + 2]), __uint_as_float(r0[4 * j + 3]));
            }
        }
    }
    __syncthreads();
    if (warp == 8) tc_dealloc(tmem, 512);
#endif  // HAS_TCGEN05
}

// ================= HMMA fallback (round-1 kernel, proven 396us) =================
#define HBM 64
#define HBN 64
#define HNIT (S_LEN / HBN)
#define LDH 264
#define TILE_H (HBM * LDH)
#define SMEM_HM (5 * TILE_H * 2)

#if !HAS_TCGEN05
__device__ __forceinline__ void ldsm4(unsigned a, unsigned& r0, unsigned& r1, unsigned& r2, unsigned& r3) {
    asm volatile("ldmatrix.sync.aligned.m8n8.x4.shared.b16 {%0,%1,%2,%3}, [%4];\n"
                 : "=r"(r0), "=r"(r1), "=r"(r2), "=r"(r3) : "r"(a));
}
__device__ __forceinline__ void ldsm4t(unsigned a, unsigned& r0, unsigned& r1, unsigned& r2, unsigned& r3) {
    asm volatile("ldmatrix.sync.aligned.m8n8.x4.trans.shared.b16 {%0,%1,%2,%3}, [%4];\n"
                 : "=r"(r0), "=r"(r1), "=r"(r2), "=r"(r3) : "r"(a));
}
__device__ __forceinline__ void mma16816(float* c, unsigned a0, unsigned a1, unsigned a2, unsigned a3,
                                         unsigned b0, unsigned b1) {
    asm volatile("mma.sync.aligned.m16n8k16.row.col.f32.f16.f16.f32 "
                 "{%0,%1,%2,%3}, {%4,%5,%6,%7}, {%8,%9}, {%0,%1,%2,%3};\n"
                 : "+f"(c[0]), "+f"(c[1]), "+f"(c[2]), "+f"(c[3])
                 : "r"(a0), "r"(a1), "r"(a2), "r"(a3), "r"(b0), "r"(b1));
}
#endif

__global__ __launch_bounds__(HTHREADS, 1)
void fa_hmma_kernel(float* __restrict__ out) {
#if !HAS_TCGEN05
    extern __shared__ __half sm[];
    __half* sQ = sm;

    const int tid = threadIdx.x;
    const int lane = tid & 31;
    const int warp = tid >> 5;
    const int mt = warp >> 1;
    const int halfsel = warp & 1;
    const int g = lane >> 2;
    const int c = lane & 3;
    const int m0blk = blockIdx.x * HBM;

    {
        const __half* gq = g_Qh + (size_t)m0blk * D_DIM;
        #pragma unroll
        for (int i = tid; i < HBM * (D_DIM / 8); i += HTHREADS) {
            int row = i >> 5, ch = i & 31;
            cp16(sptr(sQ + row * LDH + ch * 8), gq + row * D_DIM + ch * 8);
        }
        cp_commit();
    }

    auto load_tile = [&](int it, int buf) {
        const __half* gk = g_Kh + (size_t)it * HBN * D_DIM;
        const __half* gv = g_Vh + (size_t)it * HBN * D_DIM;
        __half* sK = sm + (1 + 2 * buf) * TILE_H;
        __half* sV = sm + (2 + 2 * buf) * TILE_H;
        #pragma unroll
        for (int i = tid; i < HBN * (D_DIM / 8); i += HTHREADS) {
            int row = i >> 5, ch = i & 31;
            cp16(sptr(sK + row * LDH + ch * 8), gk + row * D_DIM + ch * 8);
        }
        #pragma unroll
        for (int i = tid; i < HBN * (D_DIM / 8); i += HTHREADS) {
            int row = i >> 5, ch = i & 31;
            cp16(sptr(sV + row * LDH + ch * 8), gv + row * D_DIM + ch * 8);
        }
        cp_commit();
    };
    load_tile(0, 0);

    const int q_row = mt * 16 + (lane & 7) + ((lane >> 3) & 1) * 8;
    const int q_col = ((lane >> 4) & 1) * 8;
    const unsigned qaddr0 = sptr(sQ + q_row * LDH + q_col);
    const int k_row = ((lane >> 4) & 1) * 8 + (lane & 7);
    const int k_col = ((lane >> 3) & 1) * 8;
    const int v_row = ((lane >> 3) & 1) * 8 + (lane & 7);
    const int v_col = halfsel * 128 + ((lane >> 4) & 1) * 8;

    float o[16][4];
    #pragma unroll
    for (int i = 0; i < 16; i++) { o[i][0] = o[i][1] = o[i][2] = o[i][3] = 0.f; }
    float m0 = -INFINITY, m1 = -INFINITY, l0 = 0.f, l1 = 0.f;

    int buf = 0;
    #pragma unroll 1
    for (int it = 0; it < HNIT; ++it) {
        if (it + 1 < HNIT) {
            load_tile(it + 1, buf ^ 1);
            asm volatile("cp.async.wait_group 1;\n");
        } else {
            asm volatile("cp.async.wait_group 0;\n");
        }
        __syncthreads();

        __half* sK = sm + (1 + 2 * buf) * TILE_H;
        __half* sV = sm + (2 + 2 * buf) * TILE_H;
        const unsigned kbase = sptr(sK + k_row * LDH + k_col);
        const unsigned vbase = sptr(sV + v_row * LDH + v_col);

        float s[8][4];
        #pragma unroll
        for (int t = 0; t < 8; t++) { s[t][0] = s[t][1] = s[t][2] = s[t][3] = 0.f; }

        #pragma unroll
        for (int kc = 0; kc < 16; kc++) {
            unsigned a0, a1, a2, a3;
            ldsm4(qaddr0 + kc * 32, a0, a1, a2, a3);
            #pragma unroll
            for (int np = 0; np < 4; np++) {
                unsigned b0, b1, b2, b3;
                ldsm4(kbase + np * (16 * LDH * 2) + kc * 32, b0, b1, b2, b3);
                mma16816(s[2 * np],     a0, a1, a2, a3, b0, b1);
                mma16816(s[2 * np + 1], a0, a1, a2, a3, b2, b3);
            }
        }

        float mx0 = s[0][0], mx1 = s[0][2];
        #pragma unroll
        for (int t = 0; t < 8; t++) {
            mx0 = fmaxf(mx0, fmaxf(s[t][0], s[t][1]));
            mx1 = fmaxf(mx1, fmaxf(s[t][2], s[t][3]));
        }
        mx0 = fmaxf(mx0, __shfl_xor_sync(0xffffffffu, mx0, 1));
        mx0 = fmaxf(mx0, __shfl_xor_sync(0xffffffffu, mx0, 2));
        mx1 = fmaxf(mx1, __shfl_xor_sync(0xffffffffu, mx1, 1));
        mx1 = fmaxf(mx1, __shfl_xor_sync(0xffffffffu, mx1, 2));
        float mn0 = fmaxf(m0, mx0), mn1 = fmaxf(m1, mx1);
        float al0 = __expf(m0 - mn0), al1 = __expf(m1 - mn1);

        float rs0 = 0.f, rs1 = 0.f;
        unsigned pL[8], pH[8];
        #pragma unroll
        for (int t = 0; t < 8; t++) {
            float p00 = __expf(s[t][0] - mn0);
            float p01 = __expf(s[t][1] - mn0);
            float p10 = __expf(s[t][2] - mn1);
            float p11 = __expf(s[t][3] - mn1);
            rs0 += p00 + p01;
            rs1 += p10 + p11;
            __half2 hl = __floats2half2_rn(p00, p01);
            __half2 hh = __floats2half2_rn(p10, p11);
            pL[t] = *reinterpret_cast<unsigned*>(&hl);
            pH[t] = *reinterpret_cast<unsigned*>(&hh);
        }
        rs0 += __shfl_xor_sync(0xffffffffu, rs0, 1);
        rs0 += __shfl_xor_sync(0xffffffffu, rs0, 2);
        rs1 += __shfl_xor_sync(0xffffffffu, rs1, 1);
        rs1 += __shfl_xor_sync(0xffffffffu, rs1, 2);
        l0 = l0 * al0 + rs0;
        l1 = l1 * al1 + rs1;
        m0 = mn0; m1 = mn1;

        #pragma unroll
        for (int nt = 0; nt < 16; nt++) {
            o[nt][0] *= al0; o[nt][1] *= al0;
            o[nt][2] *= al1; o[nt][3] *= al1;
        }

        #pragma unroll
        for (int k2 = 0; k2 < 4; k2++) {
            unsigned a0 = pL[2 * k2], a1 = pH[2 * k2];
            unsigned a2 = pL[2 * k2 + 1], a3 = pH[2 * k2 + 1];
            #pragma unroll
            for (int np = 0; np < 8; np++) {
                unsigned r0, r1, r2, r3;
                ldsm4t(vbase + (k2 * 16) * (LDH * 2) + np * 32, r0, r1, r2, r3);
                mma16816(o[2 * np],     a0, a1, a2, a3, r0, r1);
                mma16816(o[2 * np + 1], a0, a1, a2, a3, r2, r3);
            }
        }

        buf ^= 1;
        __syncthreads();
    }

    float inv0 = 1.f / l0, inv1 = 1.f / l1;
    int row0 = m0blk + mt * 16 + g;
    int row1 = row0 + 8;
    #pragma unroll
    for (int nt = 0; nt < 16; nt++) {
        int col = halfsel * 128 + nt * 8 + 2 * c;
        *reinterpret_cast<float2*>(&out[(size_t)row0 * D_DIM + col]) =
            make_float2(o[nt][0] * inv0, o[nt][1] * inv0);
        *reinterpret_cast<float2*>(&out[(size_t)row1 * D_DIM + col]) =
            make_float2(o[nt][2] * inv1, o[nt][3] * inv1);
    }
#endif  // !HAS_TCGEN05
}

extern "C" void kernel_launch(void* const* d_in, const int* in_sizes, int n_in,
                              void* d_out, int out_size) {
    const float* Q = (const float*)d_in[0];
    const float* K = (const float*)d_in[1];
    const float* V = (const float*)d_in[2];
    float* out = (float*)d_out;

    int n4 = S_LEN * D_DIM / 4;
    convert_kernel<<<(n4 + 255) / 256, 256>>>(Q, K, V);
    transposeV_kernel<<<dim3(D_DIM / 32, S_LEN / 32), dim3(32, 8)>>>(V);

    cudaFuncSetAttribute(fa_tc_kernel,
                         cudaFuncAttributeMaxDynamicSharedMemorySize, SMEM_TOTAL);
    fa_tc_kernel<<<(S_LEN / BM) * NSPLIT, THREADS, SMEM_TOTAL>>>();

    combine_kernel<<<(n4 + 255) / 256, 256>>>(out);

    cudaFuncSetAttribute(fa_hmma_kernel,
                         cudaFuncAttributeMaxDynamicSharedMemorySize, SMEM_HM);
    fa_hmma_kernel<<<S_LEN / HBM, HTHREADS, SMEM_HM>>>(out);
}

// round 13
// speedup vs baseline: 1.1291x; 1.1291x over previous
#include <cuda_runtime.h>
#include <cuda_fp16.h>
#include <math.h>
#include <stdint.h>

#if defined(__CUDA_ARCH_FEAT_SM103_ALL) || defined(__CUDA_ARCH_FEAT_SM100_ALL)
#define HAS_TCGEN05 1
#else
#define HAS_TCGEN05 0
#endif

#define S_LEN 8192
#define D_DIM 256
#define BM 128
#define BN 64
#define NSPLIT 2
#define KV_PER (S_LEN / NSPLIT)
#define NIT (KV_PER / BN)
#define THREADS 384
#define HTHREADS 256

// ---------------- device scratch (allocation-free) ----------------
__device__ __half g_Qh[S_LEN * D_DIM];
__device__ __half g_Kh[S_LEN * D_DIM];
__device__ __half g_Vh[S_LEN * D_DIM];          // row-major V (HMMA fallback only)
__device__ __half g_Vt[D_DIM * S_LEN];          // transposed V (tcgen05 path)
__device__ float  g_Op[NSPLIT][S_LEN * D_DIM];  // unnormalized O per split
__device__ float  g_lsum[NSPLIT][2][S_LEN];     // partial exp-sums (per split, per col-half)

__global__ void convert_kernel(const float* __restrict__ Q,
                               const float* __restrict__ K,
                               const float* __restrict__ V) {
    int i = blockIdx.x * blockDim.x + threadIdx.x;   // over n/4
    if (i < S_LEN * D_DIM / 4) {
        const float4 q = reinterpret_cast<const float4*>(Q)[i];
        const float4 k = reinterpret_cast<const float4*>(K)[i];
#if HAS_TCGEN05
        const float scale = rsqrtf((float)S_LEN) * 1.4426950408889634f;  // fold log2(e)
        __half2* qh = reinterpret_cast<__half2*>(g_Qh) + 2 * i;
        __half2* kh = reinterpret_cast<__half2*>(g_Kh) + 2 * i;
        qh[0] = __floats2half2_rn(q.x * scale, q.y * scale);
        qh[1] = __floats2half2_rn(q.z * scale, q.w * scale);
        kh[0] = __floats2half2_rn(k.x, k.y);
        kh[1] = __floats2half2_rn(k.z, k.w);
#else
        const float scale = rsqrtf((float)S_LEN);
        const float4 v = reinterpret_cast<const float4*>(V)[i];
        __half2* qh = reinterpret_cast<__half2*>(g_Qh) + 2 * i;
        __half2* kh = reinterpret_cast<__half2*>(g_Kh) + 2 * i;
        __half2* vh = reinterpret_cast<__half2*>(g_Vh) + 2 * i;
        qh[0] = __floats2half2_rn(q.x * scale, q.y * scale);
        qh[1] = __floats2half2_rn(q.z * scale, q.w * scale);
        kh[0] = __floats2half2_rn(k.x, k.y);
        kh[1] = __floats2half2_rn(k.z, k.w);
        vh[0] = __floats2half2_rn(v.x, v.y);
        vh[1] = __floats2half2_rn(v.z, v.w);
#endif
    }
}

// V [S, D] f32 -> g_Vt [D, S] f16 (tiled transpose)
__global__ void transposeV_kernel(const float* __restrict__ V) {
    __shared__ float tile[32][33];
    const int bx = blockIdx.x * 32;   // d base
    const int by = blockIdx.y * 32;   // s base
    const int tx = threadIdx.x, ty = threadIdx.y;   // 32 x 8
    #pragma unroll
    for (int j = 0; j < 32; j += 8)
        tile[ty + j][tx] = V[(size_t)(by + ty + j) * D_DIM + bx + tx];
    __syncthreads();
    #pragma unroll
    for (int j = 0; j < 32; j += 8)
        g_Vt[(size_t)(bx + ty + j) * S_LEN + by + tx] = __float2half(tile[tx][ty + j]);
}

__global__ void combine_kernel(float* __restrict__ out) {
    int i = blockIdx.x * blockDim.x + threadIdx.x;   // over n/4
    if (i < S_LEN * D_DIM / 4) {
        int row = i >> 6;   // (4*i)>>8
        float4 a = reinterpret_cast<const float4*>(g_Op[0])[i];
        float4 b = reinterpret_cast<const float4*>(g_Op[1])[i];
        float inv = 1.f / (g_lsum[0][0][row] + g_lsum[0][1][row] +
                           g_lsum[1][0][row] + g_lsum[1][1][row]);
        float4 o;
        o.x = (a.x + b.x) * inv; o.y = (a.y + b.y) * inv;
        o.z = (a.z + b.z) * inv; o.w = (a.w + b.w) * inv;
        reinterpret_cast<float4*>(out)[i] = o;
    }
}

// ---------------- common PTX helpers ----------------
__device__ __forceinline__ uint32_t sptr(const void* p) {
    return (uint32_t)__cvta_generic_to_shared(p);
}
__device__ __forceinline__ void cp16(uint32_t s, const void* g) {
    asm volatile("cp.async.cg.shared.global [%0], [%1], 16;\n" :: "r"(s), "l"(g));
}
__device__ __forceinline__ void cp_commit() { asm volatile("cp.async.commit_group;\n"); }

#if HAS_TCGEN05
__device__ __forceinline__ void cp_wait1()  { asm volatile("cp.async.wait_group 1;\n" ::: "memory"); }
#endif
__device__ __forceinline__ void cp_wait0()  { asm volatile("cp.async.wait_group 0;\n" ::: "memory"); }

// fast exp2 via MUFU.EX2 (flag-independent)
__device__ __forceinline__ float ex2(float x) {
    float r;
    asm("ex2.approx.ftz.f32 %0, %1;" : "=f"(r) : "f"(x));
    return r;
}

#if HAS_TCGEN05
__device__ __forceinline__ void fence_proxy() {
    asm volatile("fence.proxy.async.shared::cta;" ::: "memory");
}
__device__ __forceinline__ bool elect1() {
    uint32_t p;
    asm volatile("{\n\t.reg .pred p;\n\telect.sync _|p, 0xFFFFFFFF;\n\tselp.b32 %0, 1, 0, p;\n\t}"
                 : "=r"(p));
    return p != 0;
}
__device__ __forceinline__ void mb_init(uint32_t a, uint32_t c) {
    asm volatile("mbarrier.init.shared.b64 [%0], %1;" :: "r"(a), "r"(c) : "memory");
}
__device__ __forceinline__ void mb_arrive(uint32_t a) {
    asm volatile("mbarrier.arrive.shared.b64 _, [%0];" :: "r"(a) : "memory");
}
__device__ __forceinline__ void mb_wait(uint32_t a, uint32_t ph) {
    asm volatile(
        "{\n\t.reg .pred P;\n\t"
        "WL%=:\n\t"
        "mbarrier.try_wait.parity.acquire.cta.shared::cta.b64 P, [%0], %1, 0x989680;\n\t"
        "@P bra WD%=;\n\t"
        "bra WL%=;\n\t"
        "WD%=:\n\t}"
        :: "r"(a), "r"(ph) : "memory");
}
__device__ __forceinline__ void tc_alloc(uint32_t dst, uint32_t n) {
    asm volatile("tcgen05.alloc.cta_group::1.sync.aligned.shared::cta.b32 [%0], %1;"
                 :: "r"(dst), "r"(n) : "memory");
}
__device__ __forceinline__ void tc_relinq() {
    asm volatile("tcgen05.relinquish_alloc_permit.cta_group::1.sync.aligned;");
}
__device__ __forceinline__ void tc_dealloc(uint32_t t, uint32_t n) {
    asm volatile("tcgen05.dealloc.cta_group::1.sync.aligned.b32 %0, %1;" :: "r"(t), "r"(n));
}
__device__ __forceinline__ void tc_fence_before() {
    asm volatile("tcgen05.fence::before_thread_sync;" ::: "memory");
}
__device__ __forceinline__ void tc_fence_after() {
    asm volatile("tcgen05.fence::after_thread_sync;" ::: "memory");
}
__device__ __forceinline__ void tc_wait_ld() {
    asm volatile("tcgen05.wait::ld.sync.aligned;" ::: "memory");
}
__device__ __forceinline__ void tc_wait_st() {
    asm volatile("tcgen05.wait::st.sync.aligned;" ::: "memory");
}
__device__ __forceinline__ void tc_commit(uint32_t mbar) {
    asm volatile("tcgen05.commit.cta_group::1.mbarrier::arrive::one.shared::cluster.b64 [%0];"
                 :: "r"(mbar) : "memory");
}
__device__ __forceinline__ void mma_f16_ss(uint32_t d, uint64_t a, uint64_t b,
                                           uint32_t idesc, uint32_t en) {
    asm volatile(
        "{\n\t.reg .pred p;\n\tsetp.ne.u32 p, %4, 0;\n\t"
        "tcgen05.mma.cta_group::1.kind::f16 [%0], %1, %2, %3, {%5,%5,%5,%5}, p;\n\t}"
        :: "r"(d), "l"(a), "l"(b), "r"(idesc), "r"(en), "r"(0u) : "memory");
}
__device__ __forceinline__ void mma_f16_ts(uint32_t d, uint32_t a, uint64_t b,
                                           uint32_t idesc, uint32_t en) {
    asm volatile(
        "{\n\t.reg .pred p;\n\tsetp.ne.u32 p, %4, 0;\n\t"
        "tcgen05.mma.cta_group::1.kind::f16 [%0], [%1], %2, %3, {%5,%5,%5,%5}, p;\n\t}"
        :: "r"(d), "r"(a), "l"(b), "r"(idesc), "r"(en), "r"(0u) : "memory");
}

#define LDTM_LIST "{%0,%1,%2,%3,%4,%5,%6,%7,%8,%9,%10,%11,%12,%13,%14,%15,%16,%17,%18,%19,%20,%21,%22,%23,%24,%25,%26,%27,%28,%29,%30,%31}"
__device__ __forceinline__ void ldtm32(uint32_t* r, uint32_t a) {
    asm volatile("tcgen05.ld.sync.aligned.32x32b.x32.b32 " LDTM_LIST ", [%32];"
        : "=r"(r[0]), "=r"(r[1]), "=r"(r[2]), "=r"(r[3]), "=r"(r[4]), "=r"(r[5]), "=r"(r[6]), "=r"(r[7]),
          "=r"(r[8]), "=r"(r[9]), "=r"(r[10]), "=r"(r[11]), "=r"(r[12]), "=r"(r[13]), "=r"(r[14]), "=r"(r[15]),
          "=r"(r[16]), "=r"(r[17]), "=r"(r[18]), "=r"(r[19]), "=r"(r[20]), "=r"(r[21]), "=r"(r[22]), "=r"(r[23]),
          "=r"(r[24]), "=r"(r[25]), "=r"(r[26]), "=r"(r[27]), "=r"(r[28]), "=r"(r[29]), "=r"(r[30]), "=r"(r[31])
        : "r"(a));
}
__device__ __forceinline__ void sttm16(uint32_t a, const uint32_t* r) {
    asm volatile("tcgen05.st.sync.aligned.32x32b.x16.b32 [%0], "
        "{%1,%2,%3,%4,%5,%6,%7,%8,%9,%10,%11,%12,%13,%14,%15,%16};"
        :: "r"(a),
           "r"(r[0]), "r"(r[1]), "r"(r[2]), "r"(r[3]), "r"(r[4]), "r"(r[5]), "r"(r[6]), "r"(r[7]),
           "r"(r[8]), "r"(r[9]), "r"(r[10]), "r"(r[11]), "r"(r[12]), "r"(r[13]), "r"(r[14]), "r"(r[15])
        : "memory");
}
#endif  // HAS_TCGEN05

// ---------------- tcgen05 SMEM layout (relative to 1024-aligned base) ----------------
#define SM_Q    1024
#define SM_K(s) (SM_Q + BM * D_DIM * 2 + (s) * (BN * D_DIM * 2))
#define SM_V(s) (SM_Q + BM * D_DIM * 2 + 3 * (BN * D_DIM * 2) + (s) * (BN * D_DIM * 2))
#define SMEM_TOTAL (SM_V(2) + 1024)

// mbarrier offsets (within 1KB header)
#define MB_KRDY(s)  (16 + 8 * (s))    // 3: K smem stage loaded   (count 96)
#define MB_VRDY(s)  (48 + 8 * (s))    // 2: V smem stage loaded   (count 96)
#define MB_SQK(s)   (80 + 8 * (s))    // 2: QK commit (S ready / K free)  (count 1)
#define MB_PVC(b)   (112 + 8 * (b))   // 4: PV commit (V free / P free)   (count 1)
#define MB_SFREE(s) (152 + 8 * (s))   // 2: S read by softmax     (count 256)
#define MB_PRDY(b)  (176 + 8 * (b))   // 4: P written             (count 256)

// TMEM columns: S 2x64 @0, P 4x32 @128, O 256 @256
#define TM_S(s)  (64u * (s))
#define TM_P(b)  (128u + 32u * (b))
#define TM_O     256u

// K-major blocked-atom swizzled offset. r: row, c8: 16B chunk, natr: rows/8
__device__ __forceinline__ uint32_t kmaj_off(int r, int c8, int natr) {
    uint32_t b = (uint32_t)((c8 >> 3) * natr + (r >> 3)) * 1024u
               + (uint32_t)(r & 7) * 128u + (uint32_t)(c8 & 7) * 16u;
    return b ^ ((b >> 3) & 0x70u);
}

#define DESC_KMAJ ((2ull << 61) | (1ull << 46) | (64ull << 32) | (1ull << 16))
#define IDESC_F16 ((1u << 4) | (8u << 17) | (8u << 24))   // f32 accum, f16 in, N=64, M=128

__global__ __launch_bounds__(THREADS, 1)
void fa_tc_kernel() {
#if HAS_TCGEN05
    extern __shared__ char smraw[];
    const uint32_t smb = (sptr(smraw) + 1023u) & ~1023u;
    const int tid = threadIdx.x;
    const int warp = tid >> 5, lane = tid & 31;
    const int qblk = blockIdx.x >> 1;
    const int split = blockIdx.x & 1;
    const int m0 = qblk * BM;
    const size_t kv0 = (size_t)split * KV_PER;

    if (warp == 8) { tc_alloc(smb, 512); tc_relinq(); }
    if (tid == 0) {
        #pragma unroll
        for (int s = 0; s < 3; s++) mb_init(smb + MB_KRDY(s), 96);
        #pragma unroll
        for (int s = 0; s < 2; s++) {
            mb_init(smb + MB_VRDY(s), 96);
            mb_init(smb + MB_SQK(s), 1);
            mb_init(smb + MB_SFREE(s), 256);
        }
        #pragma unroll
        for (int b = 0; b < 4; b++) {
            mb_init(smb + MB_PVC(b), 1);
            mb_init(smb + MB_PRDY(b), 256);
        }
    }
    // Q tile -> SMEM (all threads)
    {
        const __half* gq = g_Qh + (size_t)m0 * D_DIM;
        for (int i = tid; i < BM * (D_DIM / 8); i += THREADS) {
            int r = i >> 5, c8 = i & 31;
            cp16(smb + SM_Q + kmaj_off(r, c8, 16), gq + r * D_DIM + c8 * 8);
        }
        cp_commit(); cp_wait0();
    }
    fence_proxy();
    __syncthreads();
    uint32_t tmem;
    asm volatile("ld.shared.b32 %0, [%1];" : "=r"(tmem) : "r"(smb));

    if (warp >= 9) {
        // ================= loader warps (9,10,11) =================
        const int ltid = tid - 288;
        int phKf[2] = {0, 0};         // K stage free: SQK((it-3)&1) flips
        int phVf[4] = {0, 0, 0, 0};   // V stage free: PVC((it-2)&3) flips
        for (int it = 0; it < NIT; ++it) {
            const int s3 = it % 3, s2 = it & 1;
            if (it >= 3) {   // QK(it-3) done -> K smem stage (it%3) free
                const int ks = (it - 3) & 1;
                mb_wait(smb + MB_SQK(ks), phKf[ks]); phKf[ks] ^= 1;
            }
            const __half* gk = g_Kh + (kv0 + (size_t)it * BN) * D_DIM;
            const uint32_t sk = smb + SM_K(s3);
            for (int i = ltid; i < BN * (D_DIM / 8); i += 96) {
                int r = i >> 5, c8 = i & 31;
                cp16(sk + kmaj_off(r, c8, 8), gk + r * D_DIM + c8 * 8);
            }
            cp_commit();                       // group: K
            if (it >= 2) {   // PV(it-2) done -> V smem stage (it&1) free
                const int vb = (it - 2) & 3;
                mb_wait(smb + MB_PVC(vb), phVf[vb]); phVf[vb] ^= 1;
            }
            const __half* gvt = g_Vt + kv0 + (size_t)it * BN;
            const uint32_t sv = smb + SM_V(s2);
            for (int i = ltid; i < D_DIM * (BN / 8); i += 96) {
                int r = i >> 3, c8 = i & 7;
                cp16(sv + kmaj_off(r, c8, 32), gvt + (size_t)r * S_LEN + c8 * 8);
            }
            cp_commit();                       // group: V
            cp_wait1();                        // K group done
            fence_proxy();
            mb_arrive(smb + MB_KRDY(s3));
            cp_wait0();                        // V group done
            fence_proxy();
            mb_arrive(smb + MB_VRDY(s2));
        }
    } else if (warp == 8) {
        // ================= MMA issuer warp (single, round-11 structure) =================
        const uint64_t qd = DESC_KMAJ | (((uint64_t)(smb + SM_Q) >> 4) & 0x3FFFull);
        const uint64_t kd[3] = {
            DESC_KMAJ | (((uint64_t)(smb + SM_K(0)) >> 4) & 0x3FFFull),
            DESC_KMAJ | (((uint64_t)(smb + SM_K(1)) >> 4) & 0x3FFFull),
            DESC_KMAJ | (((uint64_t)(smb + SM_K(2)) >> 4) & 0x3FFFull) };
        const uint64_t vd[2] = {
            DESC_KMAJ | (((uint64_t)(smb + SM_V(0)) >> 4) & 0x3FFFull),
            DESC_KMAJ | (((uint64_t)(smb + SM_V(1)) >> 4) & 0x3FFFull) };

        int phKr[3] = {0, 0, 0};      // KRDY (K smem, mod 3)
        int phSf[2] = {0, 0};         // SFREE (S tmem, mod 2)
        int phVr[2] = {0, 0};         // VRDY (V smem, mod 2)
        int phPr[4] = {0, 0, 0, 0};   // PRDY (P tmem, mod 4)

        auto issue_qk = [&](int it) {
            const int ks = it % 3, ss = it & 1;
            mb_wait(smb + MB_KRDY(ks), phKr[ks]); phKr[ks] ^= 1;
            if (it >= 2) { mb_wait(smb + MB_SFREE(ss), phSf[ss]); phSf[ss] ^= 1; }
            tc_fence_after();
            if (elect1()) {
                for (int k = 0; k < 16; k++)
                    mma_f16_ss(tmem + TM_S(ss), qd + ((k >> 2) * 1024 + (k & 3) * 2),
                               kd[ks] + ((k >> 2) * 512 + (k & 3) * 2), IDESC_F16, k > 0);
                tc_commit(smb + MB_SQK(ss));
            }
        };

        issue_qk(0);
        if (NIT > 1) issue_qk(1);

        for (int it = 0; it < NIT; ++it) {
            const int b2 = it & 1, b4 = it & 3;
            // PV(it) first (PVC unblocks loader; PRDY now arrives early thanks
            // to 4-deep P so this wait is short).
            mb_wait(smb + MB_VRDY(b2), phVr[b2]); phVr[b2] ^= 1;
            mb_wait(smb + MB_PRDY(b4), phPr[b4]); phPr[b4] ^= 1;
            tc_fence_after();
            if (elect1()) {
                for (int c = 0; c < 4; c++)
                    for (int k = 0; k < 4; k++)
                        mma_f16_ts(tmem + TM_O + 64 * c, tmem + TM_P(b4) + 8 * k,
                                   vd[b2] + 512 * c + 2 * k, IDESC_F16, (it > 0) || (k > 0));
                tc_commit(smb + MB_PVC(b4));
            }
            if (it + 2 < NIT) issue_qk(it + 2);
        }
    } else {
        // ===== softmax warps (0-7): subpartition warp%4, column-half warp/4 =====
        // 4-deep P: sttm(it) waits only PVC(it-4) — PV completion latency is
        // off the recurring critical cycle.
        const int sub = warp & 3;
        const int half = warp >> 2;
        const uint32_t woff = (uint32_t)sub << 21;
        const uint32_t scol = (uint32_t)half * 32;   // S col offset (fp32 cols)
        const uint32_t pcol = (uint32_t)half * 16;   // P col offset (b32 = 2 f16)
        int phS[2] = {0, 0};           // SQK (S ready, mod 2)
        int phPv[4] = {0, 0, 0, 0};    // PVC (P free, mod 4)
        float lacc = 0.f;
        uint32_t rA[32], rB[32];

        auto sm_step = [&](int it, uint32_t* rc, uint32_t* rn) {
            const int b4 = it & 3;
            tc_wait_ld();                        // rc (tile it) in registers
            mb_arrive(smb + MB_SFREE(it & 1));   // S stage reusable by QK(it+2)
            uint32_t pk[16];
            #pragma unroll
            for (int j = 0; j < 16; j++) {
                float e0 = ex2(__uint_as_float(rc[2 * j]));
                float e1 = ex2(__uint_as_float(rc[2 * j + 1]));
                lacc += e0 + e1;
                __half2 h = __floats2half2_rn(e0, e1);
                pk[j] = *reinterpret_cast<uint32_t*>(&h);
            }
            if (it >= 4) { mb_wait(smb + MB_PVC(b4), phPv[b4]); phPv[b4] ^= 1; }
            tc_fence_after();
            sttm16(tmem + TM_P(b4) + woff + pcol, pk);
            tc_wait_st();
            tc_fence_before();
            mb_arrive(smb + MB_PRDY(b4));
            // prefetch S(it+1) AFTER PRDY (off PV's critical path)
            if (it + 1 < NIT) {
                const int sn = (it + 1) & 1;
                mb_wait(smb + MB_SQK(sn), phS[sn]); phS[sn] ^= 1;
                tc_fence_after();
                ldtm32(rn, tmem + TM_S(sn) + woff + scol);
            }
        };

        // prologue: load S(0)
        mb_wait(smb + MB_SQK(0), phS[0]); phS[0] ^= 1;
        tc_fence_after();
        ldtm32(rA, tmem + TM_S(0) + woff + scol);
        for (int it = 0; it < NIT; it += 2) {    // NIT even
            sm_step(it, rA, rB);
            sm_step(it + 1, rB, rA);
        }
        // epilogue: wait last PV, read O (each warp: 128 cols of its 32 rows)
        {
            const int lb = (NIT - 1) & 3;
            mb_wait(smb + MB_PVC(lb), phPv[lb]);
            tc_fence_after();
            const int row = m0 + (sub << 5) + lane;
            g_lsum[split][half][row] = lacc;
            float* op = g_Op[split] + (size_t)row * D_DIM + half * 128;
            for (int c = 0; c < 4; c++) {
                uint32_t r0[32];
                ldtm32(r0, tmem + TM_O + half * 128 + c * 32 + woff);
                tc_wait_ld();
                float4* dst = reinterpret_cast<float4*>(op + 32 * c);
                #pragma unroll
                for (int j = 0; j < 8; j++)
                    dst[j] = make_float4(__uint_as_float(r0[4 * j]), __uint_as_float(r0[4 * j + 1]),
                                         __uint_as_float(r0[4 * j + 2]), __uint_as_float(r0[4 * j + 3]));
            }
        }
    }
    __syncthreads();
    if (warp == 8) tc_dealloc(tmem, 512);
#endif  // HAS_TCGEN05
}

// ================= HMMA fallback (round-1 kernel, proven 396us) =================
#define HBM 64
#define HBN 64
#define HNIT (S_LEN / HBN)
#define LDH 264
#define TILE_H (HBM * LDH)
#define SMEM_HM (5 * TILE_H * 2)

#if !HAS_TCGEN05
__device__ __forceinline__ void ldsm4(unsigned a, unsigned& r0, unsigned& r1, unsigned& r2, unsigned& r3) {
    asm volatile("ldmatrix.sync.aligned.m8n8.x4.shared.b16 {%0,%1,%2,%3}, [%4];\n"
                 : "=r"(r0), "=r"(r1), "=r"(r2), "=r"(r3) : "r"(a));
}
__device__ __forceinline__ void ldsm4t(unsigned a, unsigned& r0, unsigned& r1, unsigned& r2, unsigned& r3) {
    asm volatile("ldmatrix.sync.aligned.m8n8.x4.trans.shared.b16 {%0,%1,%2,%3}, [%4];\n"
                 : "=r"(r0), "=r"(r1), "=r"(r2), "=r"(r3) : "r"(a));
}
__device__ __forceinline__ void mma16816(float* c, unsigned a0, unsigned a1, unsigned a2, unsigned a3,
                                         unsigned b0, unsigned b1) {
    asm volatile("mma.sync.aligned.m16n8k16.row.col.f32.f16.f16.f32 "
                 "{%0,%1,%2,%3}, {%4,%5,%6,%7}, {%8,%9}, {%0,%1,%2,%3};\n"
                 : "+f"(c[0]), "+f"(c[1]), "+f"(c[2]), "+f"(c[3])
                 : "r"(a0), "r"(a1), "r"(a2), "r"(a3), "r"(b0), "r"(b1));
}
#endif

__global__ __launch_bounds__(HTHREADS, 1)
void fa_hmma_kernel(float* __restrict__ out) {
#if !HAS_TCGEN05
    extern __shared__ __half sm[];
    __half* sQ = sm;

    const int tid = threadIdx.x;
    const int lane = tid & 31;
    const int warp = tid >> 5;
    const int mt = warp >> 1;
    const int halfsel = warp & 1;
    const int g = lane >> 2;
    const int c = lane & 3;
    const int m0blk = blockIdx.x * HBM;

    {
        const __half* gq = g_Qh + (size_t)m0blk * D_DIM;
        #pragma unroll
        for (int i = tid; i < HBM * (D_DIM / 8); i += HTHREADS) {
            int row = i >> 5, ch = i & 31;
            cp16(sptr(sQ + row * LDH + ch * 8), gq + row * D_DIM + ch * 8);
        }
        cp_commit();
    }

    auto load_tile = [&](int it, int buf) {
        const __half* gk = g_Kh + (size_t)it * HBN * D_DIM;
        const __half* gv = g_Vh + (size_t)it * HBN * D_DIM;
        __half* sK = sm + (1 + 2 * buf) * TILE_H;
        __half* sV = sm + (2 + 2 * buf) * TILE_H;
        #pragma unroll
        for (int i = tid; i < HBN * (D_DIM / 8); i += HTHREADS) {
            int row = i >> 5, ch = i & 31;
            cp16(sptr(sK + row * LDH + ch * 8), gk + row * D_DIM + ch * 8);
        }
        #pragma unroll
        for (int i = tid; i < HBN * (D_DIM / 8); i += HTHREADS) {
            int row = i >> 5, ch = i & 31;
            cp16(sptr(sV + row * LDH + ch * 8), gv + row * D_DIM + ch * 8);
        }
        cp_commit();
    };
    load_tile(0, 0);

    const int q_row = mt * 16 + (lane & 7) + ((lane >> 3) & 1) * 8;
    const int q_col = ((lane >> 4) & 1) * 8;
    const unsigned qaddr0 = sptr(sQ + q_row * LDH + q_col);
    const int k_row = ((lane >> 4) & 1) * 8 + (lane & 7);
    const int k_col = ((lane >> 3) & 1) * 8;
    const int v_row = ((lane >> 3) & 1) * 8 + (lane & 7);
    const int v_col = halfsel * 128 + ((lane >> 4) & 1) * 8;

    float o[16][4];
    #pragma unroll
    for (int i = 0; i < 16; i++) { o[i][0] = o[i][1] = o[i][2] = o[i][3] = 0.f; }
    float m0 = -INFINITY, m1 = -INFINITY, l0 = 0.f, l1 = 0.f;

    int buf = 0;
    #pragma unroll 1
    for (int it = 0; it < HNIT; ++it) {
        if (it + 1 < HNIT) {
            load_tile(it + 1, buf ^ 1);
            asm volatile("cp.async.wait_group 1;\n");
        } else {
            asm volatile("cp.async.wait_group 0;\n");
        }
        __syncthreads();

        __half* sK = sm + (1 + 2 * buf) * TILE_H;
        __half* sV = sm + (2 + 2 * buf) * TILE_H;
        const unsigned kbase = sptr(sK + k_row * LDH + k_col);
        const unsigned vbase = sptr(sV + v_row * LDH + v_col);

        float s[8][4];
        #pragma unroll
        for (int t = 0; t < 8; t++) { s[t][0] = s[t][1] = s[t][2] = s[t][3] = 0.f; }

        #pragma unroll
        for (int kc = 0; kc < 16; kc++) {
            unsigned a0, a1, a2, a3;
            ldsm4(qaddr0 + kc * 32, a0, a1, a2, a3);
            #pragma unroll
            for (int np = 0; np < 4; np++) {
                unsigned b0, b1, b2, b3;
                ldsm4(kbase + np * (16 * LDH * 2) + kc * 32, b0, b1, b2, b3);
                mma16816(s[2 * np],     a0, a1, a2, a3, b0, b1);
                mma16816(s[2 * np + 1], a0, a1, a2, a3, b2, b3);
            }
        }

        float mx0 = s[0][0], mx1 = s[0][2];
        #pragma unroll
        for (int t = 0; t < 8; t++) {
            mx0 = fmaxf(mx0, fmaxf(s[t][0], s[t][1]));
            mx1 = fmaxf(mx1, fmaxf(s[t][2], s[t][3]));
        }
        mx0 = fmaxf(mx0, __shfl_xor_sync(0xffffffffu, mx0, 1));
        mx0 = fmaxf(mx0, __shfl_xor_sync(0xffffffffu, mx0, 2));
        mx1 = fmaxf(mx1, __shfl_xor_sync(0xffffffffu, mx1, 1));
        mx1 = fmaxf(mx1, __shfl_xor_sync(0xffffffffu, mx1, 2));
        float mn0 = fmaxf(m0, mx0), mn1 = fmaxf(m1, mx1);
        float al0 = __expf(m0 - mn0), al1 = __expf(m1 - mn1);

        float rs0 = 0.f, rs1 = 0.f;
        unsigned pL[8], pH[8];
        #pragma unroll
        for (int t = 0; t < 8; t++) {
            float p00 = __expf(s[t][0] - mn0);
            float p01 = __expf(s[t][1] - mn0);
            float p10 = __expf(s[t][2] - mn1);
            float p11 = __expf(s[t][3] - mn1);
            rs0 += p00 + p01;
            rs1 += p10 + p11;
            __half2 hl = __floats2half2_rn(p00, p01);
            __half2 hh = __floats2half2_rn(p10, p11);
            pL[t] = *reinterpret_cast<unsigned*>(&hl);
            pH[t] = *reinterpret_cast<unsigned*>(&hh);
        }
        rs0 += __shfl_xor_sync(0xffffffffu, rs0, 1);
        rs0 += __shfl_xor_sync(0xffffffffu, rs0, 2);
        rs1 += __shfl_xor_sync(0xffffffffu, rs1, 1);
        rs1 += __shfl_xor_sync(0xffffffffu, rs1, 2);
        l0 = l0 * al0 + rs0;
        l1 = l1 * al1 + rs1;
        m0 = mn0; m1 = mn1;

        #pragma unroll
        for (int nt = 0; nt < 16; nt++) {
            o[nt][0] *= al0; o[nt][1] *= al0;
            o[nt][2] *= al1; o[nt][3] *= al1;
        }

        #pragma unroll
        for (int k2 = 0; k2 < 4; k2++) {
            unsigned a0 = pL[2 * k2], a1 = pH[2 * k2];
            unsigned a2 = pL[2 * k2 + 1], a3 = pH[2 * k2 + 1];
            #pragma unroll
            for (int np = 0; np < 8; np++) {
                unsigned r0, r1, r2, r3;
                ldsm4t(vbase + (k2 * 16) * (LDH * 2) + np * 32, r0, r1, r2, r3);
                mma16816(o[2 * np],     a0, a1, a2, a3, r0, r1);
                mma16816(o[2 * np + 1], a0, a1, a2, a3, r2, r3);
            }
        }

        buf ^= 1;
        __syncthreads();
    }

    float inv0 = 1.f / l0, inv1 = 1.f / l1;
    int row0 = m0blk + mt * 16 + g;
    int row1 = row0 + 8;
    #pragma unroll
    for (int nt = 0; nt < 16; nt++) {
        int col = halfsel * 128 + nt * 8 + 2 * c;
        *reinterpret_cast<float2*>(&out[(size_t)row0 * D_DIM + col]) =
            make_float2(o[nt][0] * inv0, o[nt][1] * inv0);
        *reinterpret_cast<float2*>(&out[(size_t)row1 * D_DIM + col]) =
            make_float2(o[nt][2] * inv1, o[nt][3] * inv1);
    }
#endif  // !HAS_TCGEN05
}

extern "C" void kernel_launch(void* const* d_in, const int* in_sizes, int n_in,
                              void* d_out, int out_size) {
    const float* Q = (const float*)d_in[0];
    const float* K = (const float*)d_in[1];
    const float* V = (const float*)d_in[2];
    float* out = (float*)d_out;

    int n4 = S_LEN * D_DIM / 4;
    convert_kernel<<<(n4 + 255) / 256, 256>>>(Q, K, V);
    transposeV_kernel<<<dim3(D_DIM / 32, S_LEN / 32), dim3(32, 8)>>>(V);

    cudaFuncSetAttribute(fa_tc_kernel,
                         cudaFuncAttributeMaxDynamicSharedMemorySize, SMEM_TOTAL);
    fa_tc_kernel<<<(S_LEN / BM) * NSPLIT, THREADS, SMEM_TOTAL>>>();

    combine_kernel<<<(n4 + 255) / 256, 256>>>(out);

    cudaFuncSetAttribute(fa_hmma_kernel,
                         cudaFuncAttributeMaxDynamicSharedMemorySize, SMEM_HM);
    fa_hmma_kernel<<<S_LEN / HBM, HTHREADS, SMEM_HM>>>(out);
}

// round 14
// speedup vs baseline: 1.1476x; 1.0164x over previous
#include <cuda_runtime.h>
#include <cuda_fp16.h>
#include <math.h>
#include <stdint.h>

#if defined(__CUDA_ARCH_FEAT_SM103_ALL) || defined(__CUDA_ARCH_FEAT_SM100_ALL)
#define HAS_TCGEN05 1
#else
#define HAS_TCGEN05 0
#endif

#define S_LEN 8192
#define D_DIM 256
#define BM 128
#define BN 64
#define NSPLIT 2
#define KV_PER (S_LEN / NSPLIT)
#define NIT (KV_PER / BN)
#define THREADS 384
#define HTHREADS 256
#define NCONV_BLKS ((S_LEN * D_DIM / 4) / 256)            // 2048
#define NTRANS_BLKS ((D_DIM / 32) * (S_LEN / 32))         // 2048

// ---------------- device scratch (allocation-free) ----------------
__device__ __half g_Qh[S_LEN * D_DIM];
__device__ __half g_Kh[S_LEN * D_DIM];
__device__ __half g_Vh[S_LEN * D_DIM];          // row-major V (HMMA fallback only)
__device__ __half g_Vt[D_DIM * S_LEN];          // transposed V (tcgen05 path)
__device__ float  g_Op[NSPLIT][S_LEN * D_DIM];  // unnormalized O per split
__device__ float  g_lsum[NSPLIT][2][S_LEN];     // partial exp-sums (per split, per col-half)

// Fused prep: blocks [0, NCONV_BLKS) convert Q/K (and V for fallback);
// blocks [NCONV_BLKS, NCONV_BLKS+NTRANS_BLKS) transpose V (tc path).
__global__ void prep_kernel(const float* __restrict__ Q,
                            const float* __restrict__ K,
                            const float* __restrict__ V) {
    if (blockIdx.x < NCONV_BLKS) {
        int i = blockIdx.x * blockDim.x + threadIdx.x;   // over n/4
        const float4 q = reinterpret_cast<const float4*>(Q)[i];
        const float4 k = reinterpret_cast<const float4*>(K)[i];
#if HAS_TCGEN05
        const float scale = rsqrtf((float)S_LEN) * 1.4426950408889634f;  // fold log2(e)
        __half2* qh = reinterpret_cast<__half2*>(g_Qh) + 2 * i;
        __half2* kh = reinterpret_cast<__half2*>(g_Kh) + 2 * i;
        qh[0] = __floats2half2_rn(q.x * scale, q.y * scale);
        qh[1] = __floats2half2_rn(q.z * scale, q.w * scale);
        kh[0] = __floats2half2_rn(k.x, k.y);
        kh[1] = __floats2half2_rn(k.z, k.w);
#else
        const float scale = rsqrtf((float)S_LEN);
        const float4 v = reinterpret_cast<const float4*>(V)[i];
        __half2* qh = reinterpret_cast<__half2*>(g_Qh) + 2 * i;
        __half2* kh = reinterpret_cast<__half2*>(g_Kh) + 2 * i;
        __half2* vh = reinterpret_cast<__half2*>(g_Vh) + 2 * i;
        qh[0] = __floats2half2_rn(q.x * scale, q.y * scale);
        qh[1] = __floats2half2_rn(q.z * scale, q.w * scale);
        kh[0] = __floats2half2_rn(k.x, k.y);
        kh[1] = __floats2half2_rn(k.z, k.w);
        vh[0] = __floats2half2_rn(v.x, v.y);
        vh[1] = __floats2half2_rn(v.z, v.w);
#endif
    }
#if HAS_TCGEN05
    else {
        // V [S, D] f32 -> g_Vt [D, S] f16 (32x32 tile; 256 threads as 32x8)
        __shared__ float tile[32][33];
        int b2 = blockIdx.x - NCONV_BLKS;
        const int bx = (b2 & 7) * 32;          // d base (D/32 = 8)
        const int by = (b2 >> 3) * 32;         // s base
        const int tx = threadIdx.x & 31, ty = threadIdx.x >> 5;   // 32 x 8
        #pragma unroll
        for (int j = 0; j < 32; j += 8)
            tile[ty + j][tx] = V[(size_t)(by + ty + j) * D_DIM + bx + tx];
        __syncthreads();
        #pragma unroll
        for (int j = 0; j < 32; j += 8)
            g_Vt[(size_t)(bx + ty + j) * S_LEN + by + tx] = __float2half(tile[tx][ty + j]);
    }
#endif
}

__global__ void combine_kernel(float* __restrict__ out) {
    // 2 float4 per thread for MLP=2 (latency-bound at 1 element)
    int i0 = (blockIdx.x * blockDim.x + threadIdx.x) * 2;
    #pragma unroll
    for (int u = 0; u < 2; u++) {
        int i = i0 + u;
        int row = i >> 6;   // (4*i)>>8
        float4 a = reinterpret_cast<const float4*>(g_Op[0])[i];
        float4 b = reinterpret_cast<const float4*>(g_Op[1])[i];
        float inv = 1.f / (g_lsum[0][0][row] + g_lsum[0][1][row] +
                           g_lsum[1][0][row] + g_lsum[1][1][row]);
        float4 o;
        o.x = (a.x + b.x) * inv; o.y = (a.y + b.y) * inv;
        o.z = (a.z + b.z) * inv; o.w = (a.w + b.w) * inv;
        reinterpret_cast<float4*>(out)[i] = o;
    }
}

// ---------------- common PTX helpers ----------------
__device__ __forceinline__ uint32_t sptr(const void* p) {
    return (uint32_t)__cvta_generic_to_shared(p);
}
__device__ __forceinline__ void cp16(uint32_t s, const void* g) {
    asm volatile("cp.async.cg.shared.global [%0], [%1], 16;\n" :: "r"(s), "l"(g));
}
__device__ __forceinline__ void cp_commit() { asm volatile("cp.async.commit_group;\n"); }

#if HAS_TCGEN05
__device__ __forceinline__ void cp_wait1()  { asm volatile("cp.async.wait_group 1;\n" ::: "memory"); }
#endif
__device__ __forceinline__ void cp_wait0()  { asm volatile("cp.async.wait_group 0;\n" ::: "memory"); }

// fast exp2 via MUFU.EX2 (flag-independent)
__device__ __forceinline__ float ex2(float x) {
    float r;
    asm("ex2.approx.ftz.f32 %0, %1;" : "=f"(r) : "f"(x));
    return r;
}

#if HAS_TCGEN05
__device__ __forceinline__ void fence_proxy() {
    asm volatile("fence.proxy.async.shared::cta;" ::: "memory");
}
__device__ __forceinline__ bool elect1() {
    uint32_t p;
    asm volatile("{\n\t.reg .pred p;\n\telect.sync _|p, 0xFFFFFFFF;\n\tselp.b32 %0, 1, 0, p;\n\t}"
                 : "=r"(p));
    return p != 0;
}
__device__ __forceinline__ void mb_init(uint32_t a, uint32_t c) {
    asm volatile("mbarrier.init.shared.b64 [%0], %1;" :: "r"(a), "r"(c) : "memory");
}
__device__ __forceinline__ void mb_arrive(uint32_t a) {
    asm volatile("mbarrier.arrive.shared.b64 _, [%0];" :: "r"(a) : "memory");
}
__device__ __forceinline__ void mb_wait(uint32_t a, uint32_t ph) {
    asm volatile(
        "{\n\t.reg .pred P;\n\t"
        "WL%=:\n\t"
        "mbarrier.try_wait.parity.acquire.cta.shared::cta.b64 P, [%0], %1, 0x989680;\n\t"
        "@P bra WD%=;\n\t"
        "bra WL%=;\n\t"
        "WD%=:\n\t}"
        :: "r"(a), "r"(ph) : "memory");
}
__device__ __forceinline__ void tc_alloc(uint32_t dst, uint32_t n) {
    asm volatile("tcgen05.alloc.cta_group::1.sync.aligned.shared::cta.b32 [%0], %1;"
                 :: "r"(dst), "r"(n) : "memory");
}
__device__ __forceinline__ void tc_relinq() {
    asm volatile("tcgen05.relinquish_alloc_permit.cta_group::1.sync.aligned;");
}
__device__ __forceinline__ void tc_dealloc(uint32_t t, uint32_t n) {
    asm volatile("tcgen05.dealloc.cta_group::1.sync.aligned.b32 %0, %1;" :: "r"(t), "r"(n));
}
__device__ __forceinline__ void tc_fence_before() {
    asm volatile("tcgen05.fence::before_thread_sync;" ::: "memory");
}
__device__ __forceinline__ void tc_fence_after() {
    asm volatile("tcgen05.fence::after_thread_sync;" ::: "memory");
}
__device__ __forceinline__ void tc_wait_ld() {
    asm volatile("tcgen05.wait::ld.sync.aligned;" ::: "memory");
}
__device__ __forceinline__ void tc_wait_st() {
    asm volatile("tcgen05.wait::st.sync.aligned;" ::: "memory");
}
__device__ __forceinline__ void tc_commit(uint32_t mbar) {
    asm volatile("tcgen05.commit.cta_group::1.mbarrier::arrive::one.shared::cluster.b64 [%0];"
                 :: "r"(mbar) : "memory");
}
__device__ __forceinline__ void mma_f16_ss(uint32_t d, uint64_t a, uint64_t b,
                                           uint32_t idesc, uint32_t en) {
    asm volatile(
        "{\n\t.reg .pred p;\n\tsetp.ne.u32 p, %4, 0;\n\t"
        "tcgen05.mma.cta_group::1.kind::f16 [%0], %1, %2, %3, {%5,%5,%5,%5}, p;\n\t}"
        :: "r"(d), "l"(a), "l"(b), "r"(idesc), "r"(en), "r"(0u) : "memory");
}
__device__ __forceinline__ void mma_f16_ts(uint32_t d, uint32_t a, uint64_t b,
                                           uint32_t idesc, uint32_t en) {
    asm volatile(
        "{\n\t.reg .pred p;\n\tsetp.ne.u32 p, %4, 0;\n\t"
        "tcgen05.mma.cta_group::1.kind::f16 [%0], [%1], %2, %3, {%5,%5,%5,%5}, p;\n\t}"
        :: "r"(d), "r"(a), "l"(b), "r"(idesc), "r"(en), "r"(0u) : "memory");
}

#define LDTM_LIST "{%0,%1,%2,%3,%4,%5,%6,%7,%8,%9,%10,%11,%12,%13,%14,%15,%16,%17,%18,%19,%20,%21,%22,%23,%24,%25,%26,%27,%28,%29,%30,%31}"
__device__ __forceinline__ void ldtm32(uint32_t* r, uint32_t a) {
    asm volatile("tcgen05.ld.sync.aligned.32x32b.x32.b32 " LDTM_LIST ", [%32];"
        : "=r"(r[0]), "=r"(r[1]), "=r"(r[2]), "=r"(r[3]), "=r"(r[4]), "=r"(r[5]), "=r"(r[6]), "=r"(r[7]),
          "=r"(r[8]), "=r"(r[9]), "=r"(r[10]), "=r"(r[11]), "=r"(r[12]), "=r"(r[13]), "=r"(r[14]), "=r"(r[15]),
          "=r"(r[16]), "=r"(r[17]), "=r"(r[18]), "=r"(r[19]), "=r"(r[20]), "=r"(r[21]), "=r"(r[22]), "=r"(r[23]),
          "=r"(r[24]), "=r"(r[25]), "=r"(r[26]), "=r"(r[27]), "=r"(r[28]), "=r"(r[29]), "=r"(r[30]), "=r"(r[31])
        : "r"(a));
}
__device__ __forceinline__ void sttm16(uint32_t a, const uint32_t* r) {
    asm volatile("tcgen05.st.sync.aligned.32x32b.x16.b32 [%0], "
        "{%1,%2,%3,%4,%5,%6,%7,%8,%9,%10,%11,%12,%13,%14,%15,%16};"
        :: "r"(a),
           "r"(r[0]), "r"(r[1]), "r"(r[2]), "r"(r[3]), "r"(r[4]), "r"(r[5]), "r"(r[6]), "r"(r[7]),
           "r"(r[8]), "r"(r[9]), "r"(r[10]), "r"(r[11]), "r"(r[12]), "r"(r[13]), "r"(r[14]), "r"(r[15])
        : "memory");
}
#endif  // HAS_TCGEN05

// ---------------- tcgen05 SMEM layout (relative to 1024-aligned base) ----------------
#define SM_Q    1024
#define SM_K(s) (SM_Q + BM * D_DIM * 2 + (s) * (BN * D_DIM * 2))
#define SM_V(s) (SM_Q + BM * D_DIM * 2 + 3 * (BN * D_DIM * 2) + (s) * (BN * D_DIM * 2))
#define SMEM_TOTAL (SM_V(2) + 1024)

// mbarrier offsets (within 1KB header)
#define MB_KRDY(s)  (16 + 8 * (s))    // 3: K smem stage loaded   (count 96)
#define MB_VRDY(s)  (48 + 8 * (s))    // 2: V smem stage loaded   (count 96)
#define MB_SQK(s)   (80 + 8 * (s))    // 2: QK commit (S ready / K free)  (count 1)
#define MB_PVC(b)   (112 + 8 * (b))   // 4: PV commit (V free / P free)   (count 1)
#define MB_SFREE(s) (152 + 8 * (s))   // 2: S read by softmax     (count 256)
#define MB_PRDY(b)  (176 + 8 * (b))   // 4: P written             (count 256)

// TMEM columns: S 2x64 @0, P 4x32 @128, O 256 @256
#define TM_S(s)  (64u * (s))
#define TM_P(b)  (128u + 32u * (b))
#define TM_O     256u

// K-major blocked-atom swizzled offset. r: row, c8: 16B chunk, natr: rows/8
__device__ __forceinline__ uint32_t kmaj_off(int r, int c8, int natr) {
    uint32_t b = (uint32_t)((c8 >> 3) * natr + (r >> 3)) * 1024u
               + (uint32_t)(r & 7) * 128u + (uint32_t)(c8 & 7) * 16u;
    return b ^ ((b >> 3) & 0x70u);
}

#define DESC_KMAJ ((2ull << 61) | (1ull << 46) | (64ull << 32) | (1ull << 16))
#define IDESC_F16 ((1u << 4) | (8u << 17) | (8u << 24))   // f32 accum, f16 in, N=64, M=128

__global__ __launch_bounds__(THREADS, 1)
void fa_tc_kernel() {
#if HAS_TCGEN05
    extern __shared__ char smraw[];
    const uint32_t smb = (sptr(smraw) + 1023u) & ~1023u;
    const int tid = threadIdx.x;
    const int warp = tid >> 5, lane = tid & 31;
    const int qblk = blockIdx.x >> 1;
    const int split = blockIdx.x & 1;
    const int m0 = qblk * BM;
    const size_t kv0 = (size_t)split * KV_PER;

    if (warp == 8) { tc_alloc(smb, 512); tc_relinq(); }
    if (tid == 0) {
        #pragma unroll
        for (int s = 0; s < 3; s++) mb_init(smb + MB_KRDY(s), 96);
        #pragma unroll
        for (int s = 0; s < 2; s++) {
            mb_init(smb + MB_VRDY(s), 96);
            mb_init(smb + MB_SQK(s), 1);
            mb_init(smb + MB_SFREE(s), 256);
        }
        #pragma unroll
        for (int b = 0; b < 4; b++) {
            mb_init(smb + MB_PVC(b), 1);
            mb_init(smb + MB_PRDY(b), 256);
        }
    }
    // Q tile -> SMEM (all threads)
    {
        const __half* gq = g_Qh + (size_t)m0 * D_DIM;
        for (int i = tid; i < BM * (D_DIM / 8); i += THREADS) {
            int r = i >> 5, c8 = i & 31;
            cp16(smb + SM_Q + kmaj_off(r, c8, 16), gq + r * D_DIM + c8 * 8);
        }
        cp_commit(); cp_wait0();
    }
    fence_proxy();
    __syncthreads();
    uint32_t tmem;
    asm volatile("ld.shared.b32 %0, [%1];" : "=r"(tmem) : "r"(smb));

    if (warp >= 9) {
        // ================= loader warps (9,10,11) =================
        const int ltid = tid - 288;
        int phKf[2] = {0, 0};         // K stage free: SQK((it-3)&1) flips
        int phVf[4] = {0, 0, 0, 0};   // V stage free: PVC((it-2)&3) flips
        for (int it = 0; it < NIT; ++it) {
            const int s3 = it % 3, s2 = it & 1;
            if (it >= 3) {   // QK(it-3) done -> K smem stage (it%3) free
                const int ks = (it - 3) & 1;
                mb_wait(smb + MB_SQK(ks), phKf[ks]); phKf[ks] ^= 1;
            }
            const __half* gk = g_Kh + (kv0 + (size_t)it * BN) * D_DIM;
            const uint32_t sk = smb + SM_K(s3);
            for (int i = ltid; i < BN * (D_DIM / 8); i += 96) {
                int r = i >> 5, c8 = i & 31;
                cp16(sk + kmaj_off(r, c8, 8), gk + r * D_DIM + c8 * 8);
            }
            cp_commit();                       // group: K
            if (it >= 2) {   // PV(it-2) done -> V smem stage (it&1) free
                const int vb = (it - 2) & 3;
                mb_wait(smb + MB_PVC(vb), phVf[vb]); phVf[vb] ^= 1;
            }
            const __half* gvt = g_Vt + kv0 + (size_t)it * BN;
            const uint32_t sv = smb + SM_V(s2);
            for (int i = ltid; i < D_DIM * (BN / 8); i += 96) {
                int r = i >> 3, c8 = i & 7;
                cp16(sv + kmaj_off(r, c8, 32), gvt + (size_t)r * S_LEN + c8 * 8);
            }
            cp_commit();                       // group: V
            cp_wait1();                        // K group done
            fence_proxy();
            mb_arrive(smb + MB_KRDY(s3));
            cp_wait0();                        // V group done
            fence_proxy();
            mb_arrive(smb + MB_VRDY(s2));
        }
    } else if (warp == 8) {
        // ================= MMA issuer warp =================
        const uint64_t qd = DESC_KMAJ | (((uint64_t)(smb + SM_Q) >> 4) & 0x3FFFull);
        const uint64_t kd[3] = {
            DESC_KMAJ | (((uint64_t)(smb + SM_K(0)) >> 4) & 0x3FFFull),
            DESC_KMAJ | (((uint64_t)(smb + SM_K(1)) >> 4) & 0x3FFFull),
            DESC_KMAJ | (((uint64_t)(smb + SM_K(2)) >> 4) & 0x3FFFull) };
        const uint64_t vd[2] = {
            DESC_KMAJ | (((uint64_t)(smb + SM_V(0)) >> 4) & 0x3FFFull),
            DESC_KMAJ | (((uint64_t)(smb + SM_V(1)) >> 4) & 0x3FFFull) };

        int phKr[3] = {0, 0, 0};      // KRDY (K smem, mod 3)
        int phSf[2] = {0, 0};         // SFREE (S tmem, mod 2)
        int phVr[2] = {0, 0};         // VRDY (V smem, mod 2)
        int phPr[4] = {0, 0, 0, 0};   // PRDY (P tmem, mod 4)

        auto issue_qk = [&](int it) {
            const int ks = it % 3, ss = it & 1;
            mb_wait(smb + MB_KRDY(ks), phKr[ks]); phKr[ks] ^= 1;
            if (it >= 2) { mb_wait(smb + MB_SFREE(ss), phSf[ss]); phSf[ss] ^= 1; }
            tc_fence_after();
            if (elect1()) {
                for (int k = 0; k < 16; k++)
                    mma_f16_ss(tmem + TM_S(ss), qd + ((k >> 2) * 1024 + (k & 3) * 2),
                               kd[ks] + ((k >> 2) * 512 + (k & 3) * 2), IDESC_F16, k > 0);
                tc_commit(smb + MB_SQK(ss));
            }
        };

        issue_qk(0);
        if (NIT > 1) issue_qk(1);

        for (int it = 0; it < NIT; ++it) {
            const int b2 = it & 1, b4 = it & 3;
            mb_wait(smb + MB_VRDY(b2), phVr[b2]); phVr[b2] ^= 1;
            mb_wait(smb + MB_PRDY(b4), phPr[b4]); phPr[b4] ^= 1;
            tc_fence_after();
            if (elect1()) {
                for (int c = 0; c < 4; c++)
                    for (int k = 0; k < 4; k++)
                        mma_f16_ts(tmem + TM_O + 64 * c, tmem + TM_P(b4) + 8 * k,
                                   vd[b2] + 512 * c + 2 * k, IDESC_F16, (it > 0) || (k > 0));
                tc_commit(smb + MB_PVC(b4));
            }
            if (it + 2 < NIT) issue_qk(it + 2);
        }
    } else {
        // ===== softmax warps (0-7): subpartition warp%4, column-half warp/4 =====
        const int sub = warp & 3;
        const int half = warp >> 2;
        const uint32_t woff = (uint32_t)sub << 21;
        const uint32_t scol = (uint32_t)half * 32;   // S col offset (fp32 cols)
        const uint32_t pcol = (uint32_t)half * 16;   // P col offset (b32 = 2 f16)
        int phS[2] = {0, 0};           // SQK (S ready, mod 2)
        int phPv[4] = {0, 0, 0, 0};    // PVC (P free, mod 4)
        float lacc = 0.f;
        uint32_t rA[32], rB[32];

        auto sm_step = [&](int it, uint32_t* rc, uint32_t* rn) {
            const int b4 = it & 3;
            tc_wait_ld();                        // rc (tile it) in registers
            mb_arrive(smb + MB_SFREE(it & 1));   // S stage reusable by QK(it+2)
            uint32_t pk[16];
            #pragma unroll
            for (int j = 0; j < 16; j++) {
                float e0 = ex2(__uint_as_float(rc[2 * j]));
                float e1 = ex2(__uint_as_float(rc[2 * j + 1]));
                lacc += e0 + e1;
                __half2 h = __floats2half2_rn(e0, e1);
                pk[j] = *reinterpret_cast<uint32_t*>(&h);
            }
            if (it >= 4) { mb_wait(smb + MB_PVC(b4), phPv[b4]); phPv[b4] ^= 1; }
            tc_fence_after();
            sttm16(tmem + TM_P(b4) + woff + pcol, pk);
            tc_wait_st();
            tc_fence_before();
            mb_arrive(smb + MB_PRDY(b4));
            // prefetch S(it+1) AFTER PRDY (off PV's critical path)
            if (it + 1 < NIT) {
                const int sn = (it + 1) & 1;
                mb_wait(smb + MB_SQK(sn), phS[sn]); phS[sn] ^= 1;
                tc_fence_after();
                ldtm32(rn, tmem + TM_S(sn) + woff + scol);
            }
        };

        // prologue: load S(0)
        mb_wait(smb + MB_SQK(0), phS[0]); phS[0] ^= 1;
        tc_fence_after();
        ldtm32(rA, tmem + TM_S(0) + woff + scol);
        for (int it = 0; it < NIT; it += 2) {    // NIT even
            sm_step(it, rA, rB);
            sm_step(it + 1, rB, rA);
        }
        // epilogue: wait last PV, read O batched 2-wide (reuse rA/rB)
        {
            const int lb = (NIT - 1) & 3;
            mb_wait(smb + MB_PVC(lb), phPv[lb]);
            tc_fence_after();
            const int row = m0 + (sub << 5) + lane;
            g_lsum[split][half][row] = lacc;
            float* op = g_Op[split] + (size_t)row * D_DIM + half * 128;
            #pragma unroll
            for (int c = 0; c < 4; c += 2) {
                ldtm32(rA, tmem + TM_O + half * 128 + c * 32 + woff);
                ldtm32(rB, tmem + TM_O + half * 128 + (c + 1) * 32 + woff);
                tc_wait_ld();
                float4* d0 = reinterpret_cast<float4*>(op + 32 * c);
                float4* d1 = reinterpret_cast<float4*>(op + 32 * (c + 1));
                #pragma unroll
                for (int j = 0; j < 8; j++)
                    d0[j] = make_float4(__uint_as_float(rA[4 * j]), __uint_as_float(rA[4 * j + 1]),
                                        __uint_as_float(rA[4 * j + 2]), __uint_as_float(rA[4 * j + 3]));
                #pragma unroll
                for (int j = 0; j < 8; j++)
                    d1[j] = make_float4(__uint_as_float(rB[4 * j]), __uint_as_float(rB[4 * j + 1]),
                                        __uint_as_float(rB[4 * j + 2]), __uint_as_float(rB[4 * j + 3]));
            }
        }
    }
    __syncthreads();
    if (warp == 8) tc_dealloc(tmem, 512);
#endif  // HAS_TCGEN05
}

// ================= HMMA fallback (round-1 kernel, proven 396us) =================
#define HBM 64
#define HBN 64
#define HNIT (S_LEN / HBN)
#define LDH 264
#define TILE_H (HBM * LDH)
#define SMEM_HM (5 * TILE_H * 2)

#if !HAS_TCGEN05
__device__ __forceinline__ void ldsm4(unsigned a, unsigned& r0, unsigned& r1, unsigned& r2, unsigned& r3) {
    asm volatile("ldmatrix.sync.aligned.m8n8.x4.shared.b16 {%0,%1,%2,%3}, [%4];\n"
                 : "=r"(r0), "=r"(r1), "=r"(r2), "=r"(r3) : "r"(a));
}
__device__ __forceinline__ void ldsm4t(unsigned a, unsigned& r0, unsigned& r1, unsigned& r2, unsigned& r3) {
    asm volatile("ldmatrix.sync.aligned.m8n8.x4.trans.shared.b16 {%0,%1,%2,%3}, [%4];\n"
                 : "=r"(r0), "=r"(r1), "=r"(r2), "=r"(r3) : "r"(a));
}
__device__ __forceinline__ void mma16816(float* c, unsigned a0, unsigned a1, unsigned a2, unsigned a3,
                                         unsigned b0, unsigned b1) {
    asm volatile("mma.sync.aligned.m16n8k16.row.col.f32.f16.f16.f32 "
                 "{%0,%1,%2,%3}, {%4,%5,%6,%7}, {%8,%9}, {%0,%1,%2,%3};\n"
                 : "+f"(c[0]), "+f"(c[1]), "+f"(c[2]), "+f"(c[3])
                 : "r"(a0), "r"(a1), "r"(a2), "r"(a3), "r"(b0), "r"(b1));
}
#endif

__global__ __launch_bounds__(HTHREADS, 1)
void fa_hmma_kernel(float* __restrict__ out) {
#if !HAS_TCGEN05
    extern __shared__ __half sm[];
    __half* sQ = sm;

    const int tid = threadIdx.x;
    const int lane = tid & 31;
    const int warp = tid >> 5;
    const int mt = warp >> 1;
    const int halfsel = warp & 1;
    const int g = lane >> 2;
    const int c = lane & 3;
    const int m0blk = blockIdx.x * HBM;

    {
        const __half* gq = g_Qh + (size_t)m0blk * D_DIM;
        #pragma unroll
        for (int i = tid; i < HBM * (D_DIM / 8); i += HTHREADS) {
            int row = i >> 5, ch = i & 31;
            cp16(sptr(sQ + row * LDH + ch * 8), gq + row * D_DIM + ch * 8);
        }
        cp_commit();
    }

    auto load_tile = [&](int it, int buf) {
        const __half* gk = g_Kh + (size_t)it * HBN * D_DIM;
        const __half* gv = g_Vh + (size_t)it * HBN * D_DIM;
        __half* sK = sm + (1 + 2 * buf) * TILE_H;
        __half* sV = sm + (2 + 2 * buf) * TILE_H;
        #pragma unroll
        for (int i = tid; i < HBN * (D_DIM / 8); i += HTHREADS) {
            int row = i >> 5, ch = i & 31;
            cp16(sptr(sK + row * LDH + ch * 8), gk + row * D_DIM + ch * 8);
        }
        #pragma unroll
        for (int i = tid; i < HBN * (D_DIM / 8); i += HTHREADS) {
            int row = i >> 5, ch = i & 31;
            cp16(sptr(sV + row * LDH + ch * 8), gv + row * D_DIM + ch * 8);
        }
        cp_commit();
    };
    load_tile(0, 0);

    const int q_row = mt * 16 + (lane & 7) + ((lane >> 3) & 1) * 8;
    const int q_col = ((lane >> 4) & 1) * 8;
    const unsigned qaddr0 = sptr(sQ + q_row * LDH + q_col);
    const int k_row = ((lane >> 4) & 1) * 8 + (lane & 7);
    const int k_col = ((lane >> 3) & 1) * 8;
    const int v_row = ((lane >> 3) & 1) * 8 + (lane & 7);
    const int v_col = halfsel * 128 + ((lane >> 4) & 1) * 8;

    float o[16][4];
    #pragma unroll
    for (int i = 0; i < 16; i++) { o[i][0] = o[i][1] = o[i][2] = o[i][3] = 0.f; }
    float m0 = -INFINITY, m1 = -INFINITY, l0 = 0.f, l1 = 0.f;

    int buf = 0;
    #pragma unroll 1
    for (int it = 0; it < HNIT; ++it) {
        if (it + 1 < HNIT) {
            load_tile(it + 1, buf ^ 1);
            asm volatile("cp.async.wait_group 1;\n");
        } else {
            asm volatile("cp.async.wait_group 0;\n");
        }
        __syncthreads();

        __half* sK = sm + (1 + 2 * buf) * TILE_H;
        __half* sV = sm + (2 + 2 * buf) * TILE_H;
        const unsigned kbase = sptr(sK + k_row * LDH + k_col);
        const unsigned vbase = sptr(sV + v_row * LDH + v_col);

        float s[8][4];
        #pragma unroll
        for (int t = 0; t < 8; t++) { s[t][0] = s[t][1] = s[t][2] = s[t][3] = 0.f; }

        #pragma unroll
        for (int kc = 0; kc < 16; kc++) {
            unsigned a0, a1, a2, a3;
            ldsm4(qaddr0 + kc * 32, a0, a1, a2, a3);
            #pragma unroll
            for (int np = 0; np < 4; np++) {
                unsigned b0, b1, b2, b3;
                ldsm4(kbase + np * (16 * LDH * 2) + kc * 32, b0, b1, b2, b3);
                mma16816(s[2 * np],     a0, a1, a2, a3, b0, b1);
                mma16816(s[2 * np + 1], a0, a1, a2, a3, b2, b3);
            }
        }

        float mx0 = s[0][0], mx1 = s[0][2];
        #pragma unroll
        for (int t = 0; t < 8; t++) {
            mx0 = fmaxf(mx0, fmaxf(s[t][0], s[t][1]));
            mx1 = fmaxf(mx1, fmaxf(s[t][2], s[t][3]));
        }
        mx0 = fmaxf(mx0, __shfl_xor_sync(0xffffffffu, mx0, 1));
        mx0 = fmaxf(mx0, __shfl_xor_sync(0xffffffffu, mx0, 2));
        mx1 = fmaxf(mx1, __shfl_xor_sync(0xffffffffu, mx1, 1));
        mx1 = fmaxf(mx1, __shfl_xor_sync(0xffffffffu, mx1, 2));
        float mn0 = fmaxf(m0, mx0), mn1 = fmaxf(m1, mx1);
        float al0 = __expf(m0 - mn0), al1 = __expf(m1 - mn1);

        float rs0 = 0.f, rs1 = 0.f;
        unsigned pL[8], pH[8];
        #pragma unroll
        for (int t = 0; t < 8; t++) {
            float p00 = __expf(s[t][0] - mn0);
            float p01 = __expf(s[t][1] - mn0);
            float p10 = __expf(s[t][2] - mn1);
            float p11 = __expf(s[t][3] - mn1);
            rs0 += p00 + p01;
            rs1 += p10 + p11;
            __half2 hl = __floats2half2_rn(p00, p01);
            __half2 hh = __floats2half2_rn(p10, p11);
            pL[t] = *reinterpret_cast<unsigned*>(&hl);
            pH[t] = *reinterpret_cast<unsigned*>(&hh);
        }
        rs0 += __shfl_xor_sync(0xffffffffu, rs0, 1);
        rs0 += __shfl_xor_sync(0xffffffffu, rs0, 2);
        rs1 += __shfl_xor_sync(0xffffffffu, rs1, 1);
        rs1 += __shfl_xor_sync(0xffffffffu, rs1, 2);
        l0 = l0 * al0 + rs0;
        l1 = l1 * al1 + rs1;
        m0 = mn0; m1 = mn1;

        #pragma unroll
        for (int nt = 0; nt < 16; nt++) {
            o[nt][0] *= al0; o[nt][1] *= al0;
            o[nt][2] *= al1; o[nt][3] *= al1;
        }

        #pragma unroll
        for (int k2 = 0; k2 < 4; k2++) {
            unsigned a0 = pL[2 * k2], a1 = pH[2 * k2];
            unsigned a2 = pL[2 * k2 + 1], a3 = pH[2 * k2 + 1];
            #pragma unroll
            for (int np = 0; np < 8; np++) {
                unsigned r0, r1, r2, r3;
                ldsm4t(vbase + (k2 * 16) * (LDH * 2) + np * 32, r0, r1, r2, r3);
                mma16816(o[2 * np],     a0, a1, a2, a3, r0, r1);
                mma16816(o[2 * np + 1], a0, a1, a2, a3, r2, r3);
            }
        }

        buf ^= 1;
        __syncthreads();
    }

    float inv0 = 1.f / l0, inv1 = 1.f / l1;
    int row0 = m0blk + mt * 16 + g;
    int row1 = row0 + 8;
    #pragma unroll
    for (int nt = 0; nt < 16; nt++) {
        int col = halfsel * 128 + nt * 8 + 2 * c;
        *reinterpret_cast<float2*>(&out[(size_t)row0 * D_DIM + col]) =
            make_float2(o[nt][0] * inv0, o[nt][1] * inv0);
        *reinterpret_cast<float2*>(&out[(size_t)row1 * D_DIM + col]) =
            make_float2(o[nt][2] * inv1, o[nt][3] * inv1);
    }
#endif  // !HAS_TCGEN05
}

extern "C" void kernel_launch(void* const* d_in, const int* in_sizes, int n_in,
                              void* d_out, int out_size) {
    const float* Q = (const float*)d_in[0];
    const float* K = (const float*)d_in[1];
    const float* V = (const float*)d_in[2];
    float* out = (float*)d_out;

    prep_kernel<<<NCONV_BLKS + NTRANS_BLKS, 256>>>(Q, K, V);

    cudaFuncSetAttribute(fa_tc_kernel,
                         cudaFuncAttributeMaxDynamicSharedMemorySize, SMEM_TOTAL);
    fa_tc_kernel<<<(S_LEN / BM) * NSPLIT, THREADS, SMEM_TOTAL>>>();

    int n8 = S_LEN * D_DIM / 8;   // 2 float4 per thread
    combine_kernel<<<(n8 + 255) / 256, 256>>>(out);

    cudaFuncSetAttribute(fa_hmma_kernel,
                         cudaFuncAttributeMaxDynamicSharedMemorySize, SMEM_HM);
    fa_hmma_kernel<<<S_LEN / HBM, HTHREADS, SMEM_HM>>>(out);
}